// round 1
// baseline (speedup 1.0000x reference)
#include <cuda_runtime.h>
#include <math.h>

#define BB 8
#define LL 1024
#define DD 768
#define INV_SCALE 0.03608439182435161f  /* 1/sqrt(768) */

#define BM 128
#define BN 128
#define BK 16

// ---------------- scratch (static device globals; no allocation) ----------------
__device__ float g_L[BB * LL * DD];      // tanh(lhs @ Wl^T)
__device__ float g_R[BB * LL * DD];      // tanh(rhs @ Wr^T)
__device__ float g_S[BB * LL * LL];      // scores
__device__ float g_P1[BB * LL * LL];     // row-softmax probs (l-major)
__device__ float g_P2T[BB * LL * LL];    // col-softmax probs, stored transposed [r][l]
__device__ float g_rowc[BB * LL];        // m + log(sumexp) per row
__device__ float g_colc[BB * LL];        // m + log(sumexp) per column (scaled)

__device__ __forceinline__ float fast_tanh(float x) {
    // tanh(x) = 1 - 2/(exp(2x)+1); exact limits at +/-inf via expf behavior
    return 1.0f - __fdividef(2.0f, __expf(2.0f * x) + 1.0f);
}

// ---------------- GEMM C = act(A @ B^T) ----------------
// A: M x K row-major (k contiguous), B: N x K row-major (k contiguous)
template <bool TANH>
__global__ __launch_bounds__(256) void gemm_nt(
    const float* __restrict__ A, const float* __restrict__ Bmat,
    float* __restrict__ C, int K, long sA, long sB, long sC, int ldc)
{
    __shared__ float As[BM][BK + 1];
    __shared__ float Bs[BN][BK + 1];

    const int b = blockIdx.z;
    const float* Ab = A + (long)b * sA + (long)blockIdx.y * BM * K;
    const float* Bb = Bmat + (long)b * sB + (long)blockIdx.x * BN * K;
    float* Cb = C + (long)b * sC;

    const int tid = threadIdx.x;
    const int tr = tid >> 4;       // 0..15 (row group)
    const int tc = tid & 15;       // 0..15 (col group)

    float acc[8][8];
#pragma unroll
    for (int i = 0; i < 8; ++i)
#pragma unroll
        for (int j = 0; j < 8; ++j) acc[i][j] = 0.0f;

    for (int k0 = 0; k0 < K; k0 += BK) {
#pragma unroll
        for (int i = 0; i < 2; ++i) {
            int f = tid + i * 256;           // 0..511 float4 slots
            int m = f >> 2;
            int kq = (f & 3) << 2;
            float4 v = *(const float4*)(Ab + (long)m * K + k0 + kq);
            As[m][kq + 0] = v.x; As[m][kq + 1] = v.y;
            As[m][kq + 2] = v.z; As[m][kq + 3] = v.w;
        }
#pragma unroll
        for (int i = 0; i < 2; ++i) {
            int f = tid + i * 256;
            int m = f >> 2;
            int kq = (f & 3) << 2;
            float4 v = *(const float4*)(Bb + (long)m * K + k0 + kq);
            Bs[m][kq + 0] = v.x; Bs[m][kq + 1] = v.y;
            Bs[m][kq + 2] = v.z; Bs[m][kq + 3] = v.w;
        }
        __syncthreads();

#pragma unroll
        for (int k = 0; k < BK; ++k) {
            float a[8], bb[8];
#pragma unroll
            for (int i = 0; i < 8; ++i) a[i] = As[tr * 8 + i][k];
#pragma unroll
            for (int j = 0; j < 8; ++j) bb[j] = Bs[tc * 8 + j][k];
#pragma unroll
            for (int i = 0; i < 8; ++i)
#pragma unroll
                for (int j = 0; j < 8; ++j) acc[i][j] += a[i] * bb[j];
        }
        __syncthreads();
    }

    const int colBase = blockIdx.x * BN + tc * 8;
#pragma unroll
    for (int i = 0; i < 8; ++i) {
        long row = (long)blockIdx.y * BM + tr * 8 + i;
#pragma unroll
        for (int jj = 0; jj < 2; ++jj) {
            float4 v;
            float e0 = acc[i][jj * 4 + 0], e1 = acc[i][jj * 4 + 1];
            float e2 = acc[i][jj * 4 + 2], e3 = acc[i][jj * 4 + 3];
            if (TANH) {
                e0 = fast_tanh(e0); e1 = fast_tanh(e1);
                e2 = fast_tanh(e2); e3 = fast_tanh(e3);
            }
            v.x = e0; v.y = e1; v.z = e2; v.w = e3;
            *(float4*)&Cb[row * ldc + colBase + jj * 4] = v;
        }
    }
}

// ---------------- GEMM Out = A @ B written into concat output ----------------
// A: 1024 x 1024 row-major (k contiguous), B: 1024 x 768 row-major (n contiguous)
// Out element (m, n) -> out[b*1024*1536 + m*1536 + 768 + n]
__global__ __launch_bounds__(256) void gemm_nn(
    const float* __restrict__ A, const float* __restrict__ Bmat,
    float* __restrict__ out, long sA, long sB)
{
    __shared__ float As[BM][BK + 1];
    __shared__ float Bs[BK][BN];

    const int b = blockIdx.z;
    const float* Ab = A + (long)b * sA + (long)blockIdx.y * BM * 1024;
    const float* Bb = Bmat + (long)b * sB + blockIdx.x * BN;
    float* Ob = out + (long)b * LL * 1536 + (long)blockIdx.y * BM * 1536
                + 768 + blockIdx.x * BN;

    const int tid = threadIdx.x;
    const int tr = tid >> 4;
    const int tc = tid & 15;

    float acc[8][8];
#pragma unroll
    for (int i = 0; i < 8; ++i)
#pragma unroll
        for (int j = 0; j < 8; ++j) acc[i][j] = 0.0f;

    for (int k0 = 0; k0 < 1024; k0 += BK) {
#pragma unroll
        for (int i = 0; i < 2; ++i) {
            int f = tid + i * 256;
            int m = f >> 2;
            int kq = (f & 3) << 2;
            float4 v = *(const float4*)(Ab + (long)m * 1024 + k0 + kq);
            As[m][kq + 0] = v.x; As[m][kq + 1] = v.y;
            As[m][kq + 2] = v.z; As[m][kq + 3] = v.w;
        }
#pragma unroll
        for (int i = 0; i < 2; ++i) {
            int f = tid + i * 256;
            int kr = f >> 5;
            int c4 = (f & 31) << 2;
            float4 v = *(const float4*)(Bb + (long)(k0 + kr) * DD + c4);
            *(float4*)&Bs[kr][c4] = v;
        }
        __syncthreads();

#pragma unroll
        for (int k = 0; k < BK; ++k) {
            float a[8];
#pragma unroll
            for (int i = 0; i < 8; ++i) a[i] = As[tr * 8 + i][k];
            float4 b0 = *(float4*)&Bs[k][tc * 8];
            float4 b1 = *(float4*)&Bs[k][tc * 8 + 4];
            float bb[8] = {b0.x, b0.y, b0.z, b0.w, b1.x, b1.y, b1.z, b1.w};
#pragma unroll
            for (int i = 0; i < 8; ++i)
#pragma unroll
                for (int j = 0; j < 8; ++j) acc[i][j] += a[i] * bb[j];
        }
        __syncthreads();
    }

#pragma unroll
    for (int i = 0; i < 8; ++i) {
        long row = tr * 8 + i;
#pragma unroll
        for (int jj = 0; jj < 2; ++jj) {
            float4 v;
            v.x = acc[i][jj * 4 + 0]; v.y = acc[i][jj * 4 + 1];
            v.z = acc[i][jj * 4 + 2]; v.w = acc[i][jj * 4 + 3];
            *(float4*)&Ob[row * 1536 + tc * 8 + jj * 4] = v;
        }
    }
}

// ---------------- softmax stats ----------------
__global__ void row_stats(const float* __restrict__ S, float* __restrict__ rowc)
{
    const int row = blockIdx.x;  // B*L rows
    const float* Sp = S + (size_t)row * LL;
    const int t = threadIdx.x;

    float v[4];
    float m = -1e30f;
#pragma unroll
    for (int i = 0; i < 4; ++i) {
        v[i] = Sp[t + i * 256];
        m = fmaxf(m, v[i]);
    }
    __shared__ float red[256];
    red[t] = m; __syncthreads();
    for (int s = 128; s > 0; s >>= 1) {
        if (t < s) red[t] = fmaxf(red[t], red[t + s]);
        __syncthreads();
    }
    const float M = red[0];
    __syncthreads();
    float sum = 0.0f;
#pragma unroll
    for (int i = 0; i < 4; ++i) sum += __expf(v[i] - M);
    red[t] = sum; __syncthreads();
    for (int s = 128; s > 0; s >>= 1) {
        if (t < s) red[t] += red[t + s];
        __syncthreads();
    }
    if (t == 0) rowc[row] = M + __logf(red[0]);
}

__global__ void col_stats(const float* __restrict__ S, float* __restrict__ colc)
{
    // grid (32, B), block (32, 8); column r of batch n
    const int n = blockIdx.y;
    const int tx = threadIdx.x, ty = threadIdx.y;
    const int r = blockIdx.x * 32 + tx;
    const float* Sp = S + (size_t)n * LL * LL + r;

    float m = -1e30f;
    for (int l = ty * 128; l < (ty + 1) * 128; ++l)
        m = fmaxf(m, Sp[(size_t)l * LL] * INV_SCALE);

    __shared__ float redm[8][32];
    __shared__ float reds[8][32];
    redm[ty][tx] = m; __syncthreads();
    if (ty == 0) {
        float mm = redm[0][tx];
#pragma unroll
        for (int i = 1; i < 8; ++i) mm = fmaxf(mm, redm[i][tx]);
        redm[0][tx] = mm;
    }
    __syncthreads();
    const float M = redm[0][tx];

    float s = 0.0f;
    for (int l = ty * 128; l < (ty + 1) * 128; ++l)
        s += __expf(Sp[(size_t)l * LL] * INV_SCALE - M);
    reds[ty][tx] = s; __syncthreads();
    if (ty == 0) {
        float ss = 0.0f;
#pragma unroll
        for (int i = 0; i < 8; ++i) ss += reds[i][tx];
        colc[n * LL + r] = M + __logf(ss);
    }
}

// ---------------- normalize + transpose ----------------
__global__ void transform(const float* __restrict__ S,
                          const float* __restrict__ rowc,
                          const float* __restrict__ colc,
                          float* __restrict__ P1, float* __restrict__ P2T)
{
    // grid (32, 32, B), block (32, 8); 32x32 tile (l x r)
    const int n = blockIdx.z;
    const size_t base = (size_t)n * LL * LL;
    const int l0 = blockIdx.y * 32, r0 = blockIdx.x * 32;
    const int tx = threadIdx.x, ty = threadIdx.y;

    __shared__ float tile[32][33];
    const float cc = colc[n * LL + r0 + tx];

#pragma unroll
    for (int i = 0; i < 4; ++i) {
        const int ll = ty + i * 8;
        const size_t idx = base + (size_t)(l0 + ll) * LL + r0 + tx;
        const float s = S[idx];
        P1[idx] = __expf(s - rowc[n * LL + l0 + ll]);
        tile[ll][tx] = __expf(s * INV_SCALE - cc);
    }
    __syncthreads();
#pragma unroll
    for (int i = 0; i < 4; ++i) {
        const int rr = ty + i * 8;
        P2T[base + (size_t)(r0 + rr) * LL + l0 + tx] = tile[tx][rr];
    }
}

// ---------------- passthrough copy of inputs into concat slots ----------------
__global__ void copy_in(const float4* __restrict__ lhs,
                        const float4* __restrict__ rhs,
                        float4* __restrict__ out)
{
    const int t = blockIdx.x * blockDim.x + threadIdx.x;
    const int total = BB * LL * (DD / 4);  // 1,572,864
    if (t < total) {
        const int row = t / (DD / 4);
        const int c = t % (DD / 4);
        out[(size_t)row * 384 + c] = lhs[t];
        out[(size_t)BB * LL * 384 + (size_t)row * 384 + c] = rhs[t];
    }
}

// ---------------- launch ----------------
extern "C" void kernel_launch(void* const* d_in, const int* in_sizes, int n_in,
                              void* d_out, int out_size)
{
    const float* lhs = (const float*)d_in[0];
    const float* rhs = (const float*)d_in[1];
    const float* Wl  = (const float*)d_in[2];
    const float* Wr  = (const float*)d_in[3];
    float* out = (float*)d_out;

    float *pL, *pR, *pS, *pP1, *pP2T, *prc, *pcc;
    cudaGetSymbolAddress((void**)&pL, g_L);
    cudaGetSymbolAddress((void**)&pR, g_R);
    cudaGetSymbolAddress((void**)&pS, g_S);
    cudaGetSymbolAddress((void**)&pP1, g_P1);
    cudaGetSymbolAddress((void**)&pP2T, g_P2T);
    cudaGetSymbolAddress((void**)&prc, g_rowc);
    cudaGetSymbolAddress((void**)&pcc, g_colc);

    // 1. passthrough copies
    {
        int total = BB * LL * (DD / 4);
        copy_in<<<(total + 255) / 256, 256>>>((const float4*)lhs,
                                              (const float4*)rhs,
                                              (float4*)out);
    }

    // 2. projections + tanh:  g_L = tanh(lhs @ Wl^T), g_R = tanh(rhs @ Wr^T)
    //    treated as single (8*1024) x 768 x 768 GEMM
    gemm_nt<true><<<dim3(DD / BN, (BB * LL) / BM, 1), 256>>>(
        lhs, Wl, pL, DD, 0, 0, 0, DD);
    gemm_nt<true><<<dim3(DD / BN, (BB * LL) / BM, 1), 256>>>(
        rhs, Wr, pR, DD, 0, 0, 0, DD);

    // 3. scores: per batch, S = L @ R^T  (1024 x 1024 x 768)
    gemm_nt<false><<<dim3(LL / BN, LL / BM, BB), 256>>>(
        pL, pR, pS, DD, (long)LL * DD, (long)LL * DD, (long)LL * LL, LL);

    // 4. softmax stats
    row_stats<<<BB * LL, 256>>>(pS, prc);
    col_stats<<<dim3(LL / 32, BB), dim3(32, 8)>>>(pS, pcc);

    // 5. normalized probabilities (P1 row-major, P2 transposed)
    transform<<<dim3(LL / 32, LL / 32, BB), dim3(32, 8)>>>(pS, prc, pcc, pP1, pP2T);

    // 6. attention applies, written directly into concat slots
    gemm_nn<<<dim3(DD / BN, LL / BM, BB), 256>>>(
        pP1, rhs, out, (long)LL * LL, (long)LL * DD);
    gemm_nn<<<dim3(DD / BN, LL / BM, BB), 256>>>(
        pP2T, lhs, out + (size_t)BB * LL * 1536, (long)LL * LL, (long)LL * DD);
}

// round 3
// speedup vs baseline: 2.4667x; 2.4667x over previous
#include <cuda_runtime.h>
#include <cuda_bf16.h>
#include <cstdint>
#include <math.h>

#define BB 8
#define LL 1024
#define DD 768
#define INV_SCALE 0.03608439182435161f  /* 1/sqrt(768) */

typedef __nv_bfloat16 bf16;

// ---------------------------------------------------------------------------
// scratch (device globals; no allocation)
// ---------------------------------------------------------------------------
__device__ bf16 s_lhs_hi[BB * LL * DD], s_lhs_lo[BB * LL * DD];
__device__ bf16 s_rhs_hi[BB * LL * DD], s_rhs_lo[BB * LL * DD];
__device__ bf16 s_lhsT_hi[BB * DD * LL], s_lhsT_lo[BB * DD * LL];
__device__ bf16 s_rhsT_hi[BB * DD * LL], s_rhsT_lo[BB * DD * LL];
__device__ bf16 s_Wl_hi[DD * DD], s_Wl_lo[DD * DD];
__device__ bf16 s_Wr_hi[DD * DD], s_Wr_lo[DD * DD];
__device__ bf16 g_L_hi[BB * LL * DD], g_L_lo[BB * LL * DD];
__device__ bf16 g_R_hi[BB * LL * DD], g_R_lo[BB * LL * DD];
__device__ bf16 g_P1_hi[BB * LL * LL], g_P1_lo[BB * LL * LL];
__device__ bf16 g_P2_hi[BB * LL * LL], g_P2_lo[BB * LL * LL];  // transposed [r][l]
__device__ float g_S[BB * LL * LL];
__device__ float g_rowc[BB * LL];
__device__ float g_colc[BB * LL];

__device__ __forceinline__ float fast_tanh(float x) {
    return 1.0f - __fdividef(2.0f, __expf(2.0f * x) + 1.0f);
}

__device__ __forceinline__ uint32_t smem_to_u32(const void* p) {
    uint32_t a;
    asm("{ .reg .u64 t; cvta.to.shared.u64 t, %1; cvt.u32.u64 %0, t; }"
        : "=r"(a) : "l"(p));
    return a;
}

// ---------------------------------------------------------------------------
// HMMA helpers
// ---------------------------------------------------------------------------
__device__ __forceinline__ void ldsm4(uint32_t* r, uint32_t addr) {
    asm volatile("ldmatrix.sync.aligned.m8n8.x4.shared.b16 {%0,%1,%2,%3}, [%4];"
                 : "=r"(r[0]), "=r"(r[1]), "=r"(r[2]), "=r"(r[3]) : "r"(addr));
}

__device__ __forceinline__ void mma16816(float* d, const uint32_t* a,
                                         uint32_t b0, uint32_t b1) {
    asm volatile(
        "mma.sync.aligned.m16n8k16.row.col.f32.bf16.bf16.f32 "
        "{%0,%1,%2,%3}, {%4,%5,%6,%7}, {%8,%9}, {%0,%1,%2,%3};"
        : "+f"(d[0]), "+f"(d[1]), "+f"(d[2]), "+f"(d[3])
        : "r"(a[0]), "r"(a[1]), "r"(a[2]), "r"(a[3]), "r"(b0), "r"(b1));
}

#define CP_ASYNC16(saddr, gptr) \
    asm volatile("cp.async.cg.shared.global [%0], [%1], 16;" \
        :: "r"(saddr), "l"(gptr) : "memory")
#define CP_COMMIT() asm volatile("cp.async.commit_group;" ::: "memory")
#define CP_WAIT(n) asm volatile("cp.async.wait_group %0;" :: "n"(n) : "memory")

// smem tile layout: 128 rows x 32 bf16 (64B rows), chunk = 16B unit (4/row)
// swizzled chunk = chunk ^ (row&3) ^ ((row>>2)&1)  -> conflict-free ldmatrix
__device__ __forceinline__ uint32_t tile_addr(uint32_t matbase, int row, int chunk) {
    int swz = chunk ^ (row & 3) ^ ((row >> 2) & 1);
    return matbase + row * 64 + swz * 16;
}
// ldmatrix x4 fragment address for this lane (16x16 tile at baserow, k16 group kg)
__device__ __forceinline__ uint32_t frag_addr(uint32_t matbase, int baserow,
                                              int kg, int lane) {
    int row = baserow + (lane & 7) + ((lane >> 3) & 1) * 8;
    int chunk = kg * 2 + ((lane >> 4) & 1);
    return tile_addr(matbase, row, chunk);
}

// ---------------------------------------------------------------------------
// bf16x3 HMMA GEMM.  C[M,N] = act((Ahi+Alo) @ (Bhi+Blo)^T)
// A: M x K (k contiguous) hi/lo, B: N x K (k contiguous) hi/lo.
// Block 128x128, 8 warps (4 m x 2 n), K-chunk 32, 3-stage cp.async pipeline.
// EPI 0: fp32 store to C.  EPI 1: tanh + split -> Chi/Clo bf16.
// ---------------------------------------------------------------------------
#define STAGE_BYTES 32768  /* 4 matrices x 8 KB */
#define MAT_BYTES 8192

template <int EPI>
__global__ __launch_bounds__(256, 1) void mm_bf16x3(
    const bf16* __restrict__ Ahi, const bf16* __restrict__ Alo,
    const bf16* __restrict__ Bhi, const bf16* __restrict__ Blo,
    long sA, long sB, int ldk, int nch,
    float* __restrict__ C, long sC, int ldc,
    bf16* __restrict__ Chi, bf16* __restrict__ Clo)
{
    extern __shared__ char smem[];
    const uint32_t sb = smem_to_u32(smem);
    const int tid = threadIdx.x;
    const int lane = tid & 31;
    const int wid = tid >> 5;
    const int warp_m = wid & 3;       // 4 m-groups of 32
    const int warp_n = wid >> 2;      // 2 n-groups of 64
    const int bz = blockIdx.z;

    const bf16* mats[4];
    mats[0] = Ahi + (long)bz * sA + (long)blockIdx.y * 128 * ldk;
    mats[1] = Alo + (long)bz * sA + (long)blockIdx.y * 128 * ldk;
    mats[2] = Bhi + (long)bz * sB + (long)blockIdx.x * 128 * ldk;
    mats[3] = Blo + (long)bz * sB + (long)blockIdx.x * 128 * ldk;

    // per-thread load slots: each matrix has 512 16B transfers; this thread
    // handles slots tid and tid+256.
    const int r0a = tid >> 2, c0a = tid & 3;
    const int r0b = (tid + 256) >> 2, c0b = tid & 3;

    auto load_chunk = [&](int slot, int k) {
        const uint32_t base = sb + slot * STAGE_BYTES;
        const long koff = (long)k * 32;
#pragma unroll
        for (int mat = 0; mat < 4; ++mat) {
            const bf16* g = mats[mat] + koff;
            const uint32_t mb = base + mat * MAT_BYTES;
            CP_ASYNC16(tile_addr(mb, r0a, c0a), g + (long)r0a * ldk + c0a * 8);
            CP_ASYNC16(tile_addr(mb, r0b, c0b), g + (long)r0b * ldk + c0b * 8);
        }
        CP_COMMIT();
    };

    float acc[2][8][4];
#pragma unroll
    for (int i = 0; i < 2; ++i)
#pragma unroll
        for (int j = 0; j < 8; ++j)
#pragma unroll
            for (int q = 0; q < 4; ++q) acc[i][j][q] = 0.0f;

    load_chunk(0, 0);
    load_chunk(1, 1);

#pragma unroll 1
    for (int k = 0; k < nch; ++k) {
        CP_WAIT(1);
        __syncthreads();
        if (k + 2 < nch) load_chunk((k + 2) % 3, k + 2);

        const uint32_t base = sb + (k % 3) * STAGE_BYTES;
        const uint32_t sAh = base, sAl = base + MAT_BYTES;
        const uint32_t sBh = base + 2 * MAT_BYTES, sBl = base + 3 * MAT_BYTES;

#pragma unroll
        for (int kg = 0; kg < 2; ++kg) {
            uint32_t ah[2][4], al[2][4], bh[4][4], bl[4][4];
#pragma unroll
            for (int mt = 0; mt < 2; ++mt) {
                ldsm4(ah[mt], frag_addr(sAh, warp_m * 32 + mt * 16, kg, lane));
                ldsm4(al[mt], frag_addr(sAl, warp_m * 32 + mt * 16, kg, lane));
            }
#pragma unroll
            for (int ng = 0; ng < 4; ++ng) {
                ldsm4(bh[ng], frag_addr(sBh, warp_n * 64 + ng * 16, kg, lane));
                ldsm4(bl[ng], frag_addr(sBl, warp_n * 64 + ng * 16, kg, lane));
            }
#pragma unroll
            for (int mt = 0; mt < 2; ++mt)
#pragma unroll
                for (int ng = 0; ng < 4; ++ng)
#pragma unroll
                    for (int h = 0; h < 2; ++h) {
                        float* d = acc[mt][ng * 2 + h];
                        mma16816(d, ah[mt], bh[ng][h], bh[ng][h + 2]);
                        mma16816(d, ah[mt], bl[ng][h], bl[ng][h + 2]);
                        mma16816(d, al[mt], bh[ng][h], bh[ng][h + 2]);
                    }
        }
        __syncthreads();
    }

    // ---- epilogue ----
    const int rbase = blockIdx.y * 128 + warp_m * 32 + (lane >> 2);
    const int cbase = blockIdx.x * 128 + warp_n * 64 + (lane & 3) * 2;

    if (EPI == 0) {
#pragma unroll
        for (int mt = 0; mt < 2; ++mt)
#pragma unroll
            for (int nt = 0; nt < 8; ++nt) {
                const long r = rbase + mt * 16;
                const long c = cbase + nt * 8;
                float* Cp = C + (long)bz * sC + r * ldc + c;
                *(float2*)Cp = make_float2(acc[mt][nt][0], acc[mt][nt][1]);
                *(float2*)(Cp + 8L * ldc) = make_float2(acc[mt][nt][2], acc[mt][nt][3]);
            }
    } else {
#pragma unroll
        for (int mt = 0; mt < 2; ++mt)
#pragma unroll
            for (int nt = 0; nt < 8; ++nt)
#pragma unroll
                for (int half = 0; half < 2; ++half) {
                    const long r = rbase + mt * 16 + half * 8;
                    const long c = cbase + nt * 8;
                    float v0 = fast_tanh(acc[mt][nt][half * 2 + 0]);
                    float v1 = fast_tanh(acc[mt][nt][half * 2 + 1]);
                    bf16 h0 = __float2bfloat16(v0);
                    bf16 h1 = __float2bfloat16(v1);
                    bf16 l0 = __float2bfloat16(v0 - __bfloat162float(h0));
                    bf16 l1 = __float2bfloat16(v1 - __bfloat162float(h1));
                    __nv_bfloat162 hh; hh.x = h0; hh.y = h1;
                    __nv_bfloat162 llv; llv.x = l0; llv.y = l1;
                    *(uint32_t*)(Chi + r * ldc + c) = *(uint32_t*)&hh;
                    *(uint32_t*)(Clo + r * ldc + c) = *(uint32_t*)&llv;
                }
    }
}

// ---------------------------------------------------------------------------
// split + transpose: X[b,l,d] -> Xhi/Xlo (same layout), XThi/XTlo [b,d,l]
// ---------------------------------------------------------------------------
__global__ void split_tr(const float* __restrict__ X,
                         bf16* __restrict__ Xhi, bf16* __restrict__ Xlo,
                         bf16* __restrict__ XThi, bf16* __restrict__ XTlo)
{
    const int b = blockIdx.z;
    const int d0 = blockIdx.x * 32, l0 = blockIdx.y * 32;
    const int tx = threadIdx.x, ty = threadIdx.y;
    __shared__ bf16 thi[32][33], tlo[32][33];

#pragma unroll
    for (int i = 0; i < 4; ++i) {
        const int ll = ty + 8 * i;
        const size_t idx = (size_t)b * LL * DD + (size_t)(l0 + ll) * DD + d0 + tx;
        const float x = X[idx];
        const bf16 h = __float2bfloat16(x);
        const bf16 l = __float2bfloat16(x - __bfloat162float(h));
        Xhi[idx] = h; Xlo[idx] = l;
        thi[ll][tx] = h; tlo[ll][tx] = l;
    }
    __syncthreads();
#pragma unroll
    for (int i = 0; i < 4; ++i) {
        const int dd = ty + 8 * i;
        const size_t idx = (size_t)b * DD * LL + (size_t)(d0 + dd) * LL + l0 + tx;
        XThi[idx] = thi[tx][dd];
        XTlo[idx] = tlo[tx][dd];
    }
}

__global__ void split_w(const float* __restrict__ Wl, const float* __restrict__ Wr,
                        bf16* __restrict__ Wlh, bf16* __restrict__ Wll,
                        bf16* __restrict__ Wrh, bf16* __restrict__ Wrl)
{
    const int i = blockIdx.x * blockDim.x + threadIdx.x;
    if (i < DD * DD) {
        float x = Wl[i];
        bf16 h = __float2bfloat16(x);
        Wlh[i] = h; Wll[i] = __float2bfloat16(x - __bfloat162float(h));
        x = Wr[i];
        h = __float2bfloat16(x);
        Wrh[i] = h; Wrl[i] = __float2bfloat16(x - __bfloat162float(h));
    }
}

// ---------------------------------------------------------------------------
// softmax stats
// ---------------------------------------------------------------------------
__global__ void row_stats(const float* __restrict__ S, float* __restrict__ rowc)
{
    const int row = blockIdx.x;
    const float* Sp = S + (size_t)row * LL;
    const int t = threadIdx.x;
    float v[4];
    float m = -1e30f;
#pragma unroll
    for (int i = 0; i < 4; ++i) { v[i] = Sp[t + i * 256]; m = fmaxf(m, v[i]); }
    __shared__ float red[256];
    red[t] = m; __syncthreads();
    for (int s = 128; s > 0; s >>= 1) {
        if (t < s) red[t] = fmaxf(red[t], red[t + s]);
        __syncthreads();
    }
    const float M = red[0];
    __syncthreads();
    float sum = 0.0f;
#pragma unroll
    for (int i = 0; i < 4; ++i) sum += __expf(v[i] - M);
    red[t] = sum; __syncthreads();
    for (int s = 128; s > 0; s >>= 1) {
        if (t < s) red[t] += red[t + s];
        __syncthreads();
    }
    if (t == 0) rowc[row] = M + __logf(red[0]);
}

__global__ void col_stats(const float* __restrict__ S, float* __restrict__ colc)
{
    const int b = blockIdx.y;
    const int c = blockIdx.x * 128 + threadIdx.x;
    const float* Sp = S + (size_t)b * LL * LL + c;
    float m = -1e30f, s = 0.0f;
    for (int l = 0; l < LL; ++l) {
        const float x = Sp[(size_t)l * LL] * INV_SCALE;
        if (x > m) { s = s * __expf(m - x) + 1.0f; m = x; }
        else s += __expf(x - m);
    }
    colc[b * LL + c] = m + __logf(s);
}

// normalize + split + transpose into P1(hi/lo) and P2T(hi/lo)
__global__ void transform(const float* __restrict__ S,
                          const float* __restrict__ rowc,
                          const float* __restrict__ colc,
                          bf16* __restrict__ P1h, bf16* __restrict__ P1l,
                          bf16* __restrict__ P2h, bf16* __restrict__ P2l)
{
    const int n = blockIdx.z;
    const size_t base = (size_t)n * LL * LL;
    const int l0 = blockIdx.y * 32, r0 = blockIdx.x * 32;
    const int tx = threadIdx.x, ty = threadIdx.y;
    __shared__ float tile[32][33];
    const float cc = colc[n * LL + r0 + tx];

#pragma unroll
    for (int i = 0; i < 4; ++i) {
        const int ll = ty + 8 * i;
        const size_t idx = base + (size_t)(l0 + ll) * LL + r0 + tx;
        const float s = S[idx];
        const float e1 = __expf(s - rowc[n * LL + l0 + ll]);
        const bf16 h = __float2bfloat16(e1);
        P1h[idx] = h;
        P1l[idx] = __float2bfloat16(e1 - __bfloat162float(h));
        tile[ll][tx] = s * INV_SCALE - cc;
    }
    __syncthreads();
#pragma unroll
    for (int i = 0; i < 4; ++i) {
        const int rr = ty + 8 * i;
        const float e2 = __expf(tile[tx][rr]);
        const size_t idx = base + (size_t)(r0 + rr) * LL + l0 + tx;
        const bf16 h = __float2bfloat16(e2);
        P2h[idx] = h;
        P2l[idx] = __float2bfloat16(e2 - __bfloat162float(h));
    }
}

// passthrough copy of inputs into concat slots
__global__ void copy_in(const float4* __restrict__ lhs,
                        const float4* __restrict__ rhs,
                        float4* __restrict__ out)
{
    const int t = blockIdx.x * blockDim.x + threadIdx.x;
    const int total = BB * LL * (DD / 4);
    if (t < total) {
        const int row = t / (DD / 4);
        const int c = t % (DD / 4);
        out[(size_t)row * 384 + c] = lhs[t];
        out[(size_t)BB * LL * 384 + (size_t)row * 384 + c] = rhs[t];
    }
}

// ---------------------------------------------------------------------------
// launch
// ---------------------------------------------------------------------------
extern "C" void kernel_launch(void* const* d_in, const int* in_sizes, int n_in,
                              void* d_out, int out_size)
{
    const float* lhs = (const float*)d_in[0];
    const float* rhs = (const float*)d_in[1];
    const float* Wl  = (const float*)d_in[2];
    const float* Wr  = (const float*)d_in[3];
    float* out = (float*)d_out;

    bf16 *p_lhs_h, *p_lhs_l, *p_rhs_h, *p_rhs_l;
    bf16 *p_lhsT_h, *p_lhsT_l, *p_rhsT_h, *p_rhsT_l;
    bf16 *p_Wl_h, *p_Wl_l, *p_Wr_h, *p_Wr_l;
    bf16 *p_L_h, *p_L_l, *p_R_h, *p_R_l;
    bf16 *p_P1_h, *p_P1_l, *p_P2_h, *p_P2_l;
    float *pS, *prc, *pcc;
    cudaGetSymbolAddress((void**)&p_lhs_h, s_lhs_hi);
    cudaGetSymbolAddress((void**)&p_lhs_l, s_lhs_lo);
    cudaGetSymbolAddress((void**)&p_rhs_h, s_rhs_hi);
    cudaGetSymbolAddress((void**)&p_rhs_l, s_rhs_lo);
    cudaGetSymbolAddress((void**)&p_lhsT_h, s_lhsT_hi);
    cudaGetSymbolAddress((void**)&p_lhsT_l, s_lhsT_lo);
    cudaGetSymbolAddress((void**)&p_rhsT_h, s_rhsT_hi);
    cudaGetSymbolAddress((void**)&p_rhsT_l, s_rhsT_lo);
    cudaGetSymbolAddress((void**)&p_Wl_h, s_Wl_hi);
    cudaGetSymbolAddress((void**)&p_Wl_l, s_Wl_lo);
    cudaGetSymbolAddress((void**)&p_Wr_h, s_Wr_hi);
    cudaGetSymbolAddress((void**)&p_Wr_l, s_Wr_lo);
    cudaGetSymbolAddress((void**)&p_L_h, g_L_hi);
    cudaGetSymbolAddress((void**)&p_L_l, g_L_lo);
    cudaGetSymbolAddress((void**)&p_R_h, g_R_hi);
    cudaGetSymbolAddress((void**)&p_R_l, g_R_lo);
    cudaGetSymbolAddress((void**)&p_P1_h, g_P1_hi);
    cudaGetSymbolAddress((void**)&p_P1_l, g_P1_lo);
    cudaGetSymbolAddress((void**)&p_P2_h, g_P2_hi);
    cudaGetSymbolAddress((void**)&p_P2_l, g_P2_lo);
    cudaGetSymbolAddress((void**)&pS, g_S);
    cudaGetSymbolAddress((void**)&prc, g_rowc);
    cudaGetSymbolAddress((void**)&pcc, g_colc);

    const int SMEM = 3 * STAGE_BYTES;  // 96 KB
    cudaFuncSetAttribute(mm_bf16x3<0>, cudaFuncAttributeMaxDynamicSharedMemorySize, SMEM);
    cudaFuncSetAttribute(mm_bf16x3<1>, cudaFuncAttributeMaxDynamicSharedMemorySize, SMEM);

    // 1. passthrough copies
    {
        int total = BB * LL * (DD / 4);
        copy_in<<<(total + 255) / 256, 256>>>((const float4*)lhs,
                                              (const float4*)rhs, (float4*)out);
    }

    // 2. operand prep: split + transpose
    split_tr<<<dim3(DD / 32, LL / 32, BB), dim3(32, 8)>>>(
        lhs, p_lhs_h, p_lhs_l, p_lhsT_h, p_lhsT_l);
    split_tr<<<dim3(DD / 32, LL / 32, BB), dim3(32, 8)>>>(
        rhs, p_rhs_h, p_rhs_l, p_rhsT_h, p_rhsT_l);
    split_w<<<(DD * DD + 255) / 256, 256>>>(Wl, Wr, p_Wl_h, p_Wl_l, p_Wr_h, p_Wr_l);

    // 3. projections + tanh (flattened (8*1024) x 768 x 768), outputs split bf16
    mm_bf16x3<1><<<dim3(DD / 128, (BB * LL) / 128, 1), 256, SMEM>>>(
        p_lhs_h, p_lhs_l, p_Wl_h, p_Wl_l, 0, 0, DD, DD / 32,
        nullptr, 0, DD, p_L_h, p_L_l);
    mm_bf16x3<1><<<dim3(DD / 128, (BB * LL) / 128, 1), 256, SMEM>>>(
        p_rhs_h, p_rhs_l, p_Wr_h, p_Wr_l, 0, 0, DD, DD / 32,
        nullptr, 0, DD, p_R_h, p_R_l);

    // 4. scores: per batch 1024 x 1024 x 768 -> fp32 S
    mm_bf16x3<0><<<dim3(LL / 128, LL / 128, BB), 256, SMEM>>>(
        p_L_h, p_L_l, p_R_h, p_R_l,
        (long)LL * DD, (long)LL * DD, DD, DD / 32,
        pS, (long)LL * LL, LL, nullptr, nullptr);

    // 5. softmax stats + normalized split probabilities
    row_stats<<<BB * LL, 256>>>(pS, prc);
    col_stats<<<dim3(LL / 128, BB), 128>>>(pS, pcc);
    transform<<<dim3(LL / 32, LL / 32, BB), dim3(32, 8)>>>(
        pS, prc, pcc, p_P1_h, p_P1_l, p_P2_h, p_P2_l);

    // 6. applies, written straight into the concat slots (ldc = 1536, +768 offset)
    mm_bf16x3<0><<<dim3(DD / 128, LL / 128, BB), 256, SMEM>>>(
        p_P1_h, p_P1_l, p_rhsT_h, p_rhsT_l,
        (long)LL * LL, (long)DD * LL, LL, LL / 32,
        out + DD, (long)LL * 1536, 1536, nullptr, nullptr);
    mm_bf16x3<0><<<dim3(DD / 128, LL / 128, BB), 256, SMEM>>>(
        p_P2_h, p_P2_l, p_lhsT_h, p_lhsT_l,
        (long)LL * LL, (long)DD * LL, LL, LL / 32,
        out + (size_t)BB * LL * 1536 + DD, (long)LL * 1536, 1536,
        nullptr, nullptr);
}

// round 4
// speedup vs baseline: 3.2498x; 1.3175x over previous
#include <cuda_runtime.h>
#include <cuda_bf16.h>
#include <cuda_fp16.h>
#include <cstdint>
#include <math.h>

#define BB 8
#define LL 1024
#define DD 768
#define INV_SCALE 0.03608439182435161f  /* 1/sqrt(768) */

typedef __nv_bfloat16 bf16;

// ---------------------------------------------------------------------------
// scratch (device globals; no allocation)
// ---------------------------------------------------------------------------
__device__ bf16 s_lhs_hi[BB * LL * DD], s_lhs_lo[BB * LL * DD];   // proj A
__device__ bf16 s_rhs_hi[BB * LL * DD], s_rhs_lo[BB * LL * DD];
__device__ __half s_lhsT_h[BB * DD * LL], s_lhsT_l[BB * DD * LL]; // apply B (fp16)
__device__ __half s_rhsT_h[BB * DD * LL], s_rhsT_l[BB * DD * LL];
__device__ bf16 s_Wl_hi[DD * DD], s_Wl_lo[DD * DD];
__device__ bf16 s_Wr_hi[DD * DD], s_Wr_lo[DD * DD];
__device__ bf16 g_L_hi[BB * LL * DD], g_L_lo[BB * LL * DD];
__device__ bf16 g_R_hi[BB * LL * DD], g_R_lo[BB * LL * DD];
__device__ __half g_P1[BB * LL * LL];    // row-softmax probs fp16 [l][r]
__device__ __half g_P2T[BB * LL * LL];   // col-softmax probs fp16, transposed [r][l]
__device__ float g_S[BB * LL * LL];
__device__ float g_rowc[BB * LL];
__device__ float g_colc[BB * LL];

__device__ __forceinline__ float fast_tanh(float x) {
    return 1.0f - __fdividef(2.0f, __expf(2.0f * x) + 1.0f);
}

__device__ __forceinline__ uint32_t smem_to_u32(const void* p) {
    uint32_t a;
    asm("{ .reg .u64 t; cvta.to.shared.u64 t, %1; cvt.u32.u64 %0, t; }"
        : "=r"(a) : "l"(p));
    return a;
}

// ---------------------------------------------------------------------------
// HMMA helpers
// ---------------------------------------------------------------------------
__device__ __forceinline__ void ldsm4(uint32_t* r, uint32_t addr) {
    asm volatile("ldmatrix.sync.aligned.m8n8.x4.shared.b16 {%0,%1,%2,%3}, [%4];"
                 : "=r"(r[0]), "=r"(r[1]), "=r"(r[2]), "=r"(r[3]) : "r"(addr));
}

__device__ __forceinline__ void mma16816_bf(float* d, const uint32_t* a,
                                            uint32_t b0, uint32_t b1) {
    asm volatile(
        "mma.sync.aligned.m16n8k16.row.col.f32.bf16.bf16.f32 "
        "{%0,%1,%2,%3}, {%4,%5,%6,%7}, {%8,%9}, {%0,%1,%2,%3};"
        : "+f"(d[0]), "+f"(d[1]), "+f"(d[2]), "+f"(d[3])
        : "r"(a[0]), "r"(a[1]), "r"(a[2]), "r"(a[3]), "r"(b0), "r"(b1));
}

__device__ __forceinline__ void mma16816_f16(float* d, const uint32_t* a,
                                             uint32_t b0, uint32_t b1) {
    asm volatile(
        "mma.sync.aligned.m16n8k16.row.col.f32.f16.f16.f32 "
        "{%0,%1,%2,%3}, {%4,%5,%6,%7}, {%8,%9}, {%0,%1,%2,%3};"
        : "+f"(d[0]), "+f"(d[1]), "+f"(d[2]), "+f"(d[3])
        : "r"(a[0]), "r"(a[1]), "r"(a[2]), "r"(a[3]), "r"(b0), "r"(b1));
}

#define CP_ASYNC16(saddr, gptr) \
    asm volatile("cp.async.cg.shared.global [%0], [%1], 16;" \
        :: "r"(saddr), "l"(gptr) : "memory")
#define CP_COMMIT() asm volatile("cp.async.commit_group;" ::: "memory")
#define CP_WAIT(n) asm volatile("cp.async.wait_group %0;" :: "n"(n) : "memory")

// smem tile: 128 rows x 32 b16 (64B rows), swizzled 16B chunks
__device__ __forceinline__ uint32_t tile_addr(uint32_t matbase, int row, int chunk) {
    int swz = chunk ^ (row & 3) ^ ((row >> 2) & 1);
    return matbase + row * 64 + swz * 16;
}
__device__ __forceinline__ uint32_t frag_addr(uint32_t matbase, int baserow,
                                              int kg, int lane) {
    int row = baserow + (lane & 7) + ((lane >> 3) & 1) * 8;
    int chunk = kg * 2 + ((lane >> 4) & 1);
    return tile_addr(matbase, row, chunk);
}

#define MAT_BYTES 8192

// ---------------------------------------------------------------------------
// bf16x3 HMMA GEMM (proj + scores).  C = act((Ahi+Alo) @ (Bhi+Blo)^T)
// Block 128x128, 8 warps (4m x 2n), K-chunk 32, 3-stage cp.async pipeline.
// EPI 0: fp32 store.  EPI 1: tanh + split -> Chi/Clo bf16.
// ---------------------------------------------------------------------------
#define STAGE4 32768  /* 4 matrices */

template <int EPI>
__global__ __launch_bounds__(256, 1) void mm_bf16x3(
    const bf16* __restrict__ Ahi, const bf16* __restrict__ Alo,
    const bf16* __restrict__ Bhi, const bf16* __restrict__ Blo,
    long sA, long sB, int ldk, int nch,
    float* __restrict__ C, long sC, int ldc,
    bf16* __restrict__ Chi, bf16* __restrict__ Clo)
{
    extern __shared__ char smem[];
    const uint32_t sb = smem_to_u32(smem);
    const int tid = threadIdx.x;
    const int lane = tid & 31;
    const int wid = tid >> 5;
    const int warp_m = wid & 3;
    const int warp_n = wid >> 2;
    const int bz = blockIdx.z;

    const bf16* mats[4];
    mats[0] = Ahi + (long)bz * sA + (long)blockIdx.y * 128 * ldk;
    mats[1] = Alo + (long)bz * sA + (long)blockIdx.y * 128 * ldk;
    mats[2] = Bhi + (long)bz * sB + (long)blockIdx.x * 128 * ldk;
    mats[3] = Blo + (long)bz * sB + (long)blockIdx.x * 128 * ldk;

    const int r0a = tid >> 2, c0a = tid & 3;
    const int r0b = (tid + 256) >> 2;

    auto load_chunk = [&](int slot, int k) {
        const uint32_t base = sb + slot * STAGE4;
        const long koff = (long)k * 32;
#pragma unroll
        for (int mat = 0; mat < 4; ++mat) {
            const bf16* g = mats[mat] + koff;
            const uint32_t mb = base + mat * MAT_BYTES;
            CP_ASYNC16(tile_addr(mb, r0a, c0a), g + (long)r0a * ldk + c0a * 8);
            CP_ASYNC16(tile_addr(mb, r0b, c0a), g + (long)r0b * ldk + c0a * 8);
        }
        CP_COMMIT();
    };

    float acc[2][8][4];
#pragma unroll
    for (int i = 0; i < 2; ++i)
#pragma unroll
        for (int j = 0; j < 8; ++j)
#pragma unroll
            for (int q = 0; q < 4; ++q) acc[i][j][q] = 0.0f;

    load_chunk(0, 0);
    load_chunk(1, 1);

#pragma unroll 1
    for (int k = 0; k < nch; ++k) {
        CP_WAIT(1);
        __syncthreads();
        if (k + 2 < nch) load_chunk((k + 2) % 3, k + 2);

        const uint32_t base = sb + (k % 3) * STAGE4;
        const uint32_t sAh = base, sAl = base + MAT_BYTES;
        const uint32_t sBh = base + 2 * MAT_BYTES, sBl = base + 3 * MAT_BYTES;

#pragma unroll
        for (int kg = 0; kg < 2; ++kg) {
            uint32_t ah[2][4], al[2][4], bh[4][4], bl[4][4];
#pragma unroll
            for (int mt = 0; mt < 2; ++mt) {
                ldsm4(ah[mt], frag_addr(sAh, warp_m * 32 + mt * 16, kg, lane));
                ldsm4(al[mt], frag_addr(sAl, warp_m * 32 + mt * 16, kg, lane));
            }
#pragma unroll
            for (int ng = 0; ng < 4; ++ng) {
                ldsm4(bh[ng], frag_addr(sBh, warp_n * 64 + ng * 16, kg, lane));
                ldsm4(bl[ng], frag_addr(sBl, warp_n * 64 + ng * 16, kg, lane));
            }
#pragma unroll
            for (int mt = 0; mt < 2; ++mt)
#pragma unroll
                for (int ng = 0; ng < 4; ++ng)
#pragma unroll
                    for (int h = 0; h < 2; ++h) {
                        float* d = acc[mt][ng * 2 + h];
                        mma16816_bf(d, ah[mt], bh[ng][h], bh[ng][h + 2]);
                        mma16816_bf(d, ah[mt], bl[ng][h], bl[ng][h + 2]);
                        mma16816_bf(d, al[mt], bh[ng][h], bh[ng][h + 2]);
                    }
        }
        __syncthreads();
    }

    const int rbase = blockIdx.y * 128 + warp_m * 32 + (lane >> 2);
    const int cbase = blockIdx.x * 128 + warp_n * 64 + (lane & 3) * 2;

    if (EPI == 0) {
#pragma unroll
        for (int mt = 0; mt < 2; ++mt)
#pragma unroll
            for (int nt = 0; nt < 8; ++nt) {
                const long r = rbase + mt * 16;
                const long c = cbase + nt * 8;
                float* Cp = C + (long)bz * sC + r * ldc + c;
                *(float2*)Cp = make_float2(acc[mt][nt][0], acc[mt][nt][1]);
                *(float2*)(Cp + 8L * ldc) = make_float2(acc[mt][nt][2], acc[mt][nt][3]);
            }
    } else {
#pragma unroll
        for (int mt = 0; mt < 2; ++mt)
#pragma unroll
            for (int nt = 0; nt < 8; ++nt)
#pragma unroll
                for (int half = 0; half < 2; ++half) {
                    const long r = rbase + mt * 16 + half * 8;
                    const long c = cbase + nt * 8;
                    float v0 = fast_tanh(acc[mt][nt][half * 2 + 0]);
                    float v1 = fast_tanh(acc[mt][nt][half * 2 + 1]);
                    bf16 h0 = __float2bfloat16(v0);
                    bf16 h1 = __float2bfloat16(v1);
                    bf16 l0 = __float2bfloat16(v0 - __bfloat162float(h0));
                    bf16 l1 = __float2bfloat16(v1 - __bfloat162float(h1));
                    __nv_bfloat162 hh; hh.x = h0; hh.y = h1;
                    __nv_bfloat162 llv; llv.x = l0; llv.y = l1;
                    *(uint32_t*)(Chi + r * ldc + c) = *(uint32_t*)&hh;
                    *(uint32_t*)(Clo + r * ldc + c) = *(uint32_t*)&llv;
                }
    }
}

// ---------------------------------------------------------------------------
// fp16 asym-2 apply GEMM: out = P @ (Vhi+Vlo)^T
// P: M x K fp16 single, V: N x K fp16 hi/lo.  2 MMAs per step.
// Writes fp32 into strided concat output.
// ---------------------------------------------------------------------------
#define STAGE3 24576  /* 3 matrices */

__global__ __launch_bounds__(256, 1) void mm_f16_apply(
    const __half* __restrict__ P,
    const __half* __restrict__ Vhi, const __half* __restrict__ Vlo,
    float* __restrict__ out)
{
    extern __shared__ char smem[];
    const uint32_t sb = smem_to_u32(smem);
    const int tid = threadIdx.x;
    const int lane = tid & 31;
    const int wid = tid >> 5;
    const int warp_m = wid & 3;
    const int warp_n = wid >> 2;
    const int bz = blockIdx.z;

    const __half* mats[3];
    mats[0] = P + (long)bz * LL * LL + (long)blockIdx.y * 128 * LL;
    mats[1] = Vhi + (long)bz * DD * LL + (long)blockIdx.x * 128 * LL;
    mats[2] = Vlo + (long)bz * DD * LL + (long)blockIdx.x * 128 * LL;

    const int r0a = tid >> 2, c0a = tid & 3;
    const int r0b = (tid + 256) >> 2;

    auto load_chunk = [&](int slot, int k) {
        const uint32_t base = sb + slot * STAGE3;
        const long koff = (long)k * 32;
#pragma unroll
        for (int mat = 0; mat < 3; ++mat) {
            const __half* g = mats[mat] + koff;
            const uint32_t mb = base + mat * MAT_BYTES;
            CP_ASYNC16(tile_addr(mb, r0a, c0a), g + (long)r0a * LL + c0a * 8);
            CP_ASYNC16(tile_addr(mb, r0b, c0a), g + (long)r0b * LL + c0a * 8);
        }
        CP_COMMIT();
    };

    float acc[2][8][4];
#pragma unroll
    for (int i = 0; i < 2; ++i)
#pragma unroll
        for (int j = 0; j < 8; ++j)
#pragma unroll
            for (int q = 0; q < 4; ++q) acc[i][j][q] = 0.0f;

    load_chunk(0, 0);
    load_chunk(1, 1);

#pragma unroll 1
    for (int k = 0; k < 32; ++k) {
        CP_WAIT(1);
        __syncthreads();
        if (k + 2 < 32) load_chunk((k + 2) % 3, k + 2);

        const uint32_t base = sb + (k % 3) * STAGE3;
        const uint32_t sP = base;
        const uint32_t sVh = base + MAT_BYTES, sVl = base + 2 * MAT_BYTES;

#pragma unroll
        for (int kg = 0; kg < 2; ++kg) {
            uint32_t a[2][4], bh[4][4], bl[4][4];
#pragma unroll
            for (int mt = 0; mt < 2; ++mt)
                ldsm4(a[mt], frag_addr(sP, warp_m * 32 + mt * 16, kg, lane));
#pragma unroll
            for (int ng = 0; ng < 4; ++ng) {
                ldsm4(bh[ng], frag_addr(sVh, warp_n * 64 + ng * 16, kg, lane));
                ldsm4(bl[ng], frag_addr(sVl, warp_n * 64 + ng * 16, kg, lane));
            }
#pragma unroll
            for (int mt = 0; mt < 2; ++mt)
#pragma unroll
                for (int ng = 0; ng < 4; ++ng)
#pragma unroll
                    for (int h = 0; h < 2; ++h) {
                        float* d = acc[mt][ng * 2 + h];
                        mma16816_f16(d, a[mt], bh[ng][h], bh[ng][h + 2]);
                        mma16816_f16(d, a[mt], bl[ng][h], bl[ng][h + 2]);
                    }
        }
        __syncthreads();
    }

    // epilogue: fp32 strided store into concat slot (ld 1536, +768 col offset)
    const int rbase = blockIdx.y * 128 + warp_m * 32 + (lane >> 2);
    const int cbase = blockIdx.x * 128 + warp_n * 64 + (lane & 3) * 2;
    float* Ob = out + (long)bz * LL * 1536 + DD;
#pragma unroll
    for (int mt = 0; mt < 2; ++mt)
#pragma unroll
        for (int nt = 0; nt < 8; ++nt) {
            const long r = rbase + mt * 16;
            const long c = cbase + nt * 8;
            float* Cp = Ob + r * 1536 + c;
            *(float2*)Cp = make_float2(acc[mt][nt][0], acc[mt][nt][1]);
            *(float2*)(Cp + 8L * 1536) = make_float2(acc[mt][nt][2], acc[mt][nt][3]);
        }
}

// ---------------------------------------------------------------------------
// split + transpose + passthrough:
//  X[b,l,d] -> Xhi/Xlo bf16 (row-major), XTh/XTl fp16 [b,d,l], out passthrough
// ---------------------------------------------------------------------------
__global__ void split_tr(const float* __restrict__ X,
                         bf16* __restrict__ Xhi, bf16* __restrict__ Xlo,
                         __half* __restrict__ XTh, __half* __restrict__ XTl,
                         float* __restrict__ outbase)
{
    const int b = blockIdx.z;
    const int d0 = blockIdx.x * 32, l0 = blockIdx.y * 32;
    const int tx = threadIdx.x, ty = threadIdx.y;
    __shared__ __half thi[32][33], tlo[32][33];

#pragma unroll
    for (int i = 0; i < 4; ++i) {
        const int ll = ty + 8 * i;
        const size_t idx = (size_t)b * LL * DD + (size_t)(l0 + ll) * DD + d0 + tx;
        const float x = X[idx];
        // bf16 hi/lo for proj GEMM A
        const bf16 h = __float2bfloat16(x);
        Xhi[idx] = h;
        Xlo[idx] = __float2bfloat16(x - __bfloat162float(h));
        // fp16 hi/lo for apply GEMM B (transposed)
        const __half fh = __float2half(x);
        thi[ll][tx] = fh;
        tlo[ll][tx] = __float2half(x - __half2float(fh));
        // passthrough into concat slot
        outbase[(size_t)(b * LL + l0 + ll) * 1536 + d0 + tx] = x;
    }
    __syncthreads();
#pragma unroll
    for (int i = 0; i < 4; ++i) {
        const int dd = ty + 8 * i;
        const size_t idx = (size_t)b * DD * LL + (size_t)(d0 + dd) * LL + l0 + tx;
        XTh[idx] = thi[tx][dd];
        XTl[idx] = tlo[tx][dd];
    }
}

__global__ void split_w(const float* __restrict__ Wl, const float* __restrict__ Wr,
                        bf16* __restrict__ Wlh, bf16* __restrict__ Wll,
                        bf16* __restrict__ Wrh, bf16* __restrict__ Wrl)
{
    const int i = blockIdx.x * blockDim.x + threadIdx.x;
    if (i < DD * DD) {
        float x = Wl[i];
        bf16 h = __float2bfloat16(x);
        Wlh[i] = h; Wll[i] = __float2bfloat16(x - __bfloat162float(h));
        x = Wr[i];
        h = __float2bfloat16(x);
        Wrh[i] = h; Wrl[i] = __float2bfloat16(x - __bfloat162float(h));
    }
}

// ---------------------------------------------------------------------------
// softmax stats
// ---------------------------------------------------------------------------
__global__ void row_stats(const float* __restrict__ S, float* __restrict__ rowc)
{
    const int row = blockIdx.x;
    const float* Sp = S + (size_t)row * LL;
    const int t = threadIdx.x;
    float v[4];
    float m = -1e30f;
#pragma unroll
    for (int i = 0; i < 4; ++i) { v[i] = Sp[t + i * 256]; m = fmaxf(m, v[i]); }
    __shared__ float red[256];
    red[t] = m; __syncthreads();
    for (int s = 128; s > 0; s >>= 1) {
        if (t < s) red[t] = fmaxf(red[t], red[t + s]);
        __syncthreads();
    }
    const float M = red[0];
    __syncthreads();
    float sum = 0.0f;
#pragma unroll
    for (int i = 0; i < 4; ++i) sum += __expf(v[i] - M);
    red[t] = sum; __syncthreads();
    for (int s = 128; s > 0; s >>= 1) {
        if (t < s) red[t] += red[t + s];
        __syncthreads();
    }
    if (t == 0) rowc[row] = M + __logf(red[0]);
}

__global__ void col_stats(const float* __restrict__ S, float* __restrict__ colc)
{
    // grid (LL/32, BB), block (32, 8); column c of batch b
    const int b = blockIdx.y;
    const int tx = threadIdx.x, ty = threadIdx.y;
    const int c = blockIdx.x * 32 + tx;
    const float* Sp = S + (size_t)b * LL * LL + c;

    float m = -1e30f, s = 0.0f;
    for (int l = ty * 128; l < (ty + 1) * 128; ++l) {
        const float x = Sp[(size_t)l * LL] * INV_SCALE;
        if (x > m) { s = s * __expf(m - x) + 1.0f; m = x; }
        else s += __expf(x - m);
    }
    __shared__ float redm[8][32], reds[8][32];
    redm[ty][tx] = m; reds[ty][tx] = s;
    __syncthreads();
    if (ty == 0) {
        float M = redm[0][tx];
#pragma unroll
        for (int i = 1; i < 8; ++i) M = fmaxf(M, redm[i][tx]);
        float ss = 0.0f;
#pragma unroll
        for (int i = 0; i < 8; ++i) ss += reds[i][tx] * __expf(redm[i][tx] - M);
        colc[b * LL + c] = M + __logf(ss);
    }
}

// normalize into P1 fp16 [l][r] and P2T fp16 [r][l]
__global__ void transform(const float* __restrict__ S,
                          const float* __restrict__ rowc,
                          const float* __restrict__ colc,
                          __half* __restrict__ P1, __half* __restrict__ P2T)
{
    const int n = blockIdx.z;
    const size_t base = (size_t)n * LL * LL;
    const int l0 = blockIdx.y * 32, r0 = blockIdx.x * 32;
    const int tx = threadIdx.x, ty = threadIdx.y;
    __shared__ float tile[32][33];
    const float cc = colc[n * LL + r0 + tx];

#pragma unroll
    for (int i = 0; i < 4; ++i) {
        const int ll = ty + 8 * i;
        const size_t idx = base + (size_t)(l0 + ll) * LL + r0 + tx;
        const float s = S[idx];
        P1[idx] = __float2half(__expf(s - rowc[n * LL + l0 + ll]));
        tile[ll][tx] = s * INV_SCALE - cc;
    }
    __syncthreads();
#pragma unroll
    for (int i = 0; i < 4; ++i) {
        const int rr = ty + 8 * i;
        P2T[base + (size_t)(r0 + rr) * LL + l0 + tx] = __float2half(__expf(tile[tx][rr]));
    }
}

// ---------------------------------------------------------------------------
// launch
// ---------------------------------------------------------------------------
extern "C" void kernel_launch(void* const* d_in, const int* in_sizes, int n_in,
                              void* d_out, int out_size)
{
    const float* lhs = (const float*)d_in[0];
    const float* rhs = (const float*)d_in[1];
    const float* Wl  = (const float*)d_in[2];
    const float* Wr  = (const float*)d_in[3];
    float* out = (float*)d_out;

    bf16 *p_lhs_h, *p_lhs_l, *p_rhs_h, *p_rhs_l;
    __half *p_lhsT_h, *p_lhsT_l, *p_rhsT_h, *p_rhsT_l;
    bf16 *p_Wl_h, *p_Wl_l, *p_Wr_h, *p_Wr_l;
    bf16 *p_L_h, *p_L_l, *p_R_h, *p_R_l;
    __half *p_P1, *p_P2T;
    float *pS, *prc, *pcc;
    cudaGetSymbolAddress((void**)&p_lhs_h, s_lhs_hi);
    cudaGetSymbolAddress((void**)&p_lhs_l, s_lhs_lo);
    cudaGetSymbolAddress((void**)&p_rhs_h, s_rhs_hi);
    cudaGetSymbolAddress((void**)&p_rhs_l, s_rhs_lo);
    cudaGetSymbolAddress((void**)&p_lhsT_h, s_lhsT_h);
    cudaGetSymbolAddress((void**)&p_lhsT_l, s_lhsT_l);
    cudaGetSymbolAddress((void**)&p_rhsT_h, s_rhsT_h);
    cudaGetSymbolAddress((void**)&p_rhsT_l, s_rhsT_l);
    cudaGetSymbolAddress((void**)&p_Wl_h, s_Wl_hi);
    cudaGetSymbolAddress((void**)&p_Wl_l, s_Wl_lo);
    cudaGetSymbolAddress((void**)&p_Wr_h, s_Wr_hi);
    cudaGetSymbolAddress((void**)&p_Wr_l, s_Wr_lo);
    cudaGetSymbolAddress((void**)&p_L_h, g_L_hi);
    cudaGetSymbolAddress((void**)&p_L_l, g_L_lo);
    cudaGetSymbolAddress((void**)&p_R_h, g_R_hi);
    cudaGetSymbolAddress((void**)&p_R_l, g_R_lo);
    cudaGetSymbolAddress((void**)&p_P1, g_P1);
    cudaGetSymbolAddress((void**)&p_P2T, g_P2T);
    cudaGetSymbolAddress((void**)&pS, g_S);
    cudaGetSymbolAddress((void**)&prc, g_rowc);
    cudaGetSymbolAddress((void**)&pcc, g_colc);

    const int SMEM4 = 3 * STAGE4;  // 96 KB
    const int SMEM3 = 3 * STAGE3;  // 72 KB
    cudaFuncSetAttribute(mm_bf16x3<0>, cudaFuncAttributeMaxDynamicSharedMemorySize, SMEM4);
    cudaFuncSetAttribute(mm_bf16x3<1>, cudaFuncAttributeMaxDynamicSharedMemorySize, SMEM4);
    cudaFuncSetAttribute(mm_f16_apply, cudaFuncAttributeMaxDynamicSharedMemorySize, SMEM3);

    // 1. operand prep: split + transpose + passthrough copy
    split_tr<<<dim3(DD / 32, LL / 32, BB), dim3(32, 8)>>>(
        lhs, p_lhs_h, p_lhs_l, p_lhsT_h, p_lhsT_l, out);
    split_tr<<<dim3(DD / 32, LL / 32, BB), dim3(32, 8)>>>(
        rhs, p_rhs_h, p_rhs_l, p_rhsT_h, p_rhsT_l, out + (size_t)BB * LL * 1536);
    split_w<<<(DD * DD + 255) / 256, 256>>>(Wl, Wr, p_Wl_h, p_Wl_l, p_Wr_h, p_Wr_l);

    // 2. projections + tanh (flattened (8*1024) x 768 x 768), outputs split bf16
    mm_bf16x3<1><<<dim3(DD / 128, (BB * LL) / 128, 1), 256, SMEM4>>>(
        p_lhs_h, p_lhs_l, p_Wl_h, p_Wl_l, 0, 0, DD, DD / 32,
        nullptr, 0, DD, p_L_h, p_L_l);
    mm_bf16x3<1><<<dim3(DD / 128, (BB * LL) / 128, 1), 256, SMEM4>>>(
        p_rhs_h, p_rhs_l, p_Wr_h, p_Wr_l, 0, 0, DD, DD / 32,
        nullptr, 0, DD, p_R_h, p_R_l);

    // 3. scores: per batch 1024 x 1024 x 768 -> fp32 S
    mm_bf16x3<0><<<dim3(LL / 128, LL / 128, BB), 256, SMEM4>>>(
        p_L_h, p_L_l, p_R_h, p_R_l,
        (long)LL * DD, (long)LL * DD, DD, DD / 32,
        pS, (long)LL * LL, LL, nullptr, nullptr);

    // 4. softmax stats + normalized fp16 probabilities
    row_stats<<<BB * LL, 256>>>(pS, prc);
    col_stats<<<dim3(LL / 32, BB), dim3(32, 8)>>>(pS, pcc);
    transform<<<dim3(LL / 32, LL / 32, BB), dim3(32, 8)>>>(pS, prc, pcc, p_P1, p_P2T);

    // 5. applies (fp16 asym-2), written straight into the concat slots
    mm_f16_apply<<<dim3(DD / 128, LL / 128, BB), 256, SMEM3>>>(
        p_P1, p_rhsT_h, p_rhsT_l, out);
    mm_f16_apply<<<dim3(DD / 128, LL / 128, BB), 256, SMEM3>>>(
        p_P2T, p_lhsT_h, p_lhsT_l, out + (size_t)BB * LL * 1536);
}

// round 5
// speedup vs baseline: 3.4861x; 1.0727x over previous
#include <cuda_runtime.h>
#include <cuda_bf16.h>
#include <cuda_fp16.h>
#include <cstdint>
#include <math.h>

#define BB 8
#define LL 1024
#define DD 768
#define INV_SCALE 0.03608439182435161f  /* 1/sqrt(768) */

typedef __nv_bfloat16 bf16;

// ---------------------------------------------------------------------------
// scratch (device globals; no allocation)
// ---------------------------------------------------------------------------
__device__ bf16 s_lhs_hi[BB * LL * DD], s_lhs_lo[BB * LL * DD];   // proj A
__device__ bf16 s_rhs_hi[BB * LL * DD], s_rhs_lo[BB * LL * DD];
__device__ __half s_lhsT_h[BB * DD * LL], s_lhsT_l[BB * DD * LL]; // apply B (fp16)
__device__ __half s_rhsT_h[BB * DD * LL], s_rhsT_l[BB * DD * LL];
__device__ bf16 s_Wl_hi[DD * DD], s_Wl_lo[DD * DD];
__device__ bf16 s_Wr_hi[DD * DD], s_Wr_lo[DD * DD];
__device__ bf16 g_L_hi[BB * LL * DD], g_L_lo[BB * LL * DD];
__device__ bf16 g_R_hi[BB * LL * DD], g_R_lo[BB * LL * DD];
__device__ __half g_P1[BB * LL * LL];    // row-softmax probs fp16 [l][r]
__device__ __half g_P2T[BB * LL * LL];   // col-softmax probs fp16, transposed [r][l]
__device__ float g_S[BB * LL * LL];
__device__ float g_rowc[BB * LL];
__device__ float g_colc[BB * LL];

__device__ __forceinline__ float fast_tanh(float x) {
    return 1.0f - __fdividef(2.0f, __expf(2.0f * x) + 1.0f);
}

__device__ __forceinline__ uint32_t smem_to_u32(const void* p) {
    uint32_t a;
    asm("{ .reg .u64 t; cvta.to.shared.u64 t, %1; cvt.u32.u64 %0, t; }"
        : "=r"(a) : "l"(p));
    return a;
}

// ---------------------------------------------------------------------------
// HMMA helpers
// ---------------------------------------------------------------------------
__device__ __forceinline__ void ldsm4(uint32_t* r, uint32_t addr) {
    asm volatile("ldmatrix.sync.aligned.m8n8.x4.shared.b16 {%0,%1,%2,%3}, [%4];"
                 : "=r"(r[0]), "=r"(r[1]), "=r"(r[2]), "=r"(r[3]) : "r"(addr));
}

__device__ __forceinline__ void mma16816_bf(float* d, const uint32_t* a,
                                            uint32_t b0, uint32_t b1) {
    asm volatile(
        "mma.sync.aligned.m16n8k16.row.col.f32.bf16.bf16.f32 "
        "{%0,%1,%2,%3}, {%4,%5,%6,%7}, {%8,%9}, {%0,%1,%2,%3};"
        : "+f"(d[0]), "+f"(d[1]), "+f"(d[2]), "+f"(d[3])
        : "r"(a[0]), "r"(a[1]), "r"(a[2]), "r"(a[3]), "r"(b0), "r"(b1));
}

__device__ __forceinline__ void mma16816_f16(float* d, const uint32_t* a,
                                             uint32_t b0, uint32_t b1) {
    asm volatile(
        "mma.sync.aligned.m16n8k16.row.col.f32.f16.f16.f32 "
        "{%0,%1,%2,%3}, {%4,%5,%6,%7}, {%8,%9}, {%0,%1,%2,%3};"
        : "+f"(d[0]), "+f"(d[1]), "+f"(d[2]), "+f"(d[3])
        : "r"(a[0]), "r"(a[1]), "r"(a[2]), "r"(a[3]), "r"(b0), "r"(b1));
}

#define CP_ASYNC16(saddr, gptr) \
    asm volatile("cp.async.cg.shared.global [%0], [%1], 16;" \
        :: "r"(saddr), "l"(gptr) : "memory")
#define CP_COMMIT() asm volatile("cp.async.commit_group;" ::: "memory")
#define CP_WAIT(n) asm volatile("cp.async.wait_group %0;" :: "n"(n) : "memory")

// smem tile: 128 rows x 32 b16 (64B rows), swizzled 16B chunks
__device__ __forceinline__ uint32_t tile_addr(uint32_t matbase, int row, int chunk) {
    int swz = chunk ^ (row & 3) ^ ((row >> 2) & 1);
    return matbase + row * 64 + swz * 16;
}
__device__ __forceinline__ uint32_t frag_addr(uint32_t matbase, int baserow,
                                              int kg, int lane) {
    int row = baserow + (lane & 7) + ((lane >> 3) & 1) * 8;
    int chunk = kg * 2 + ((lane >> 4) & 1);
    return tile_addr(matbase, row, chunk);
}

#define MAT_BYTES 8192

// ---------------------------------------------------------------------------
// bf16x3 HMMA GEMM (proj + scores).  C = act((Ahi+Alo) @ (Bhi+Blo)^T)
// Block 128x128, 8 warps (4m x 2n), K-chunk 32, 3-stage cp.async pipeline.
// 2 CTAs/SM.  EPI 0: fp32 store.  EPI 1: tanh + split -> Chi/Clo bf16.
// ---------------------------------------------------------------------------
#define STAGE4 32768  /* 4 matrices */

template <int EPI>
__global__ __launch_bounds__(256, 2) void mm_bf16x3(
    const bf16* __restrict__ Ahi, const bf16* __restrict__ Alo,
    const bf16* __restrict__ Bhi, const bf16* __restrict__ Blo,
    long sA, long sB, int ldk, int nch,
    float* __restrict__ C, long sC, int ldc,
    bf16* __restrict__ Chi, bf16* __restrict__ Clo)
{
    extern __shared__ char smem[];
    const uint32_t sb = smem_to_u32(smem);
    const int tid = threadIdx.x;
    const int lane = tid & 31;
    const int wid = tid >> 5;
    const int warp_m = wid & 3;
    const int warp_n = wid >> 2;
    const int bz = blockIdx.z;

    const bf16* mats[4];
    mats[0] = Ahi + (long)bz * sA + (long)blockIdx.y * 128 * ldk;
    mats[1] = Alo + (long)bz * sA + (long)blockIdx.y * 128 * ldk;
    mats[2] = Bhi + (long)bz * sB + (long)blockIdx.x * 128 * ldk;
    mats[3] = Blo + (long)bz * sB + (long)blockIdx.x * 128 * ldk;

    const int r0a = tid >> 2, c0a = tid & 3;
    const int r0b = (tid + 256) >> 2;

    auto load_chunk = [&](int slot, int k) {
        const uint32_t base = sb + slot * STAGE4;
        const long koff = (long)k * 32;
#pragma unroll
        for (int mat = 0; mat < 4; ++mat) {
            const bf16* g = mats[mat] + koff;
            const uint32_t mb = base + mat * MAT_BYTES;
            CP_ASYNC16(tile_addr(mb, r0a, c0a), g + (long)r0a * ldk + c0a * 8);
            CP_ASYNC16(tile_addr(mb, r0b, c0a), g + (long)r0b * ldk + c0a * 8);
        }
        CP_COMMIT();
    };

    float acc[2][8][4];
#pragma unroll
    for (int i = 0; i < 2; ++i)
#pragma unroll
        for (int j = 0; j < 8; ++j)
#pragma unroll
            for (int q = 0; q < 4; ++q) acc[i][j][q] = 0.0f;

    load_chunk(0, 0);
    load_chunk(1, 1);

#pragma unroll 1
    for (int k = 0; k < nch; ++k) {
        CP_WAIT(1);
        __syncthreads();   // single barrier per iter: orders stage-k visibility
                           // AND all reads of stage k-1 before its overwrite
        if (k + 2 < nch) load_chunk((k + 2) % 3, k + 2);

        const uint32_t base = sb + (k % 3) * STAGE4;
        const uint32_t sAh = base, sAl = base + MAT_BYTES;
        const uint32_t sBh = base + 2 * MAT_BYTES, sBl = base + 3 * MAT_BYTES;

#pragma unroll
        for (int kg = 0; kg < 2; ++kg) {
            uint32_t ah[2][4], al[2][4], bh[4][4], bl[4][4];
#pragma unroll
            for (int mt = 0; mt < 2; ++mt) {
                ldsm4(ah[mt], frag_addr(sAh, warp_m * 32 + mt * 16, kg, lane));
                ldsm4(al[mt], frag_addr(sAl, warp_m * 32 + mt * 16, kg, lane));
            }
#pragma unroll
            for (int ng = 0; ng < 4; ++ng) {
                ldsm4(bh[ng], frag_addr(sBh, warp_n * 64 + ng * 16, kg, lane));
                ldsm4(bl[ng], frag_addr(sBl, warp_n * 64 + ng * 16, kg, lane));
            }
#pragma unroll
            for (int mt = 0; mt < 2; ++mt)
#pragma unroll
                for (int ng = 0; ng < 4; ++ng)
#pragma unroll
                    for (int h = 0; h < 2; ++h) {
                        float* d = acc[mt][ng * 2 + h];
                        mma16816_bf(d, ah[mt], bh[ng][h], bh[ng][h + 2]);
                        mma16816_bf(d, ah[mt], bl[ng][h], bl[ng][h + 2]);
                        mma16816_bf(d, al[mt], bh[ng][h], bh[ng][h + 2]);
                    }
        }
    }
    __syncthreads();

    const int rbase = blockIdx.y * 128 + warp_m * 32 + (lane >> 2);
    const int cbase = blockIdx.x * 128 + warp_n * 64 + (lane & 3) * 2;

    if (EPI == 0) {
#pragma unroll
        for (int mt = 0; mt < 2; ++mt)
#pragma unroll
            for (int nt = 0; nt < 8; ++nt) {
                const long r = rbase + mt * 16;
                const long c = cbase + nt * 8;
                float* Cp = C + (long)bz * sC + r * ldc + c;
                *(float2*)Cp = make_float2(acc[mt][nt][0], acc[mt][nt][1]);
                *(float2*)(Cp + 8L * ldc) = make_float2(acc[mt][nt][2], acc[mt][nt][3]);
            }
    } else {
#pragma unroll
        for (int mt = 0; mt < 2; ++mt)
#pragma unroll
            for (int nt = 0; nt < 8; ++nt)
#pragma unroll
                for (int half = 0; half < 2; ++half) {
                    const long r = rbase + mt * 16 + half * 8;
                    const long c = cbase + nt * 8;
                    float v0 = fast_tanh(acc[mt][nt][half * 2 + 0]);
                    float v1 = fast_tanh(acc[mt][nt][half * 2 + 1]);
                    bf16 h0 = __float2bfloat16(v0);
                    bf16 h1 = __float2bfloat16(v1);
                    bf16 l0 = __float2bfloat16(v0 - __bfloat162float(h0));
                    bf16 l1 = __float2bfloat16(v1 - __bfloat162float(h1));
                    __nv_bfloat162 hh; hh.x = h0; hh.y = h1;
                    __nv_bfloat162 llv; llv.x = l0; llv.y = l1;
                    *(uint32_t*)(Chi + r * ldc + c) = *(uint32_t*)&hh;
                    *(uint32_t*)(Clo + r * ldc + c) = *(uint32_t*)&llv;
                }
    }
}

// ---------------------------------------------------------------------------
// fp16 asym-2 apply GEMM: out = P @ (Vhi+Vlo)^T, 2 CTAs/SM
// ---------------------------------------------------------------------------
#define STAGE3 24576  /* 3 matrices */

__global__ __launch_bounds__(256, 2) void mm_f16_apply(
    const __half* __restrict__ P,
    const __half* __restrict__ Vhi, const __half* __restrict__ Vlo,
    float* __restrict__ out)
{
    extern __shared__ char smem[];
    const uint32_t sb = smem_to_u32(smem);
    const int tid = threadIdx.x;
    const int lane = tid & 31;
    const int wid = tid >> 5;
    const int warp_m = wid & 3;
    const int warp_n = wid >> 2;
    const int bz = blockIdx.z;

    const __half* mats[3];
    mats[0] = P + (long)bz * LL * LL + (long)blockIdx.y * 128 * LL;
    mats[1] = Vhi + (long)bz * DD * LL + (long)blockIdx.x * 128 * LL;
    mats[2] = Vlo + (long)bz * DD * LL + (long)blockIdx.x * 128 * LL;

    const int r0a = tid >> 2, c0a = tid & 3;
    const int r0b = (tid + 256) >> 2;

    auto load_chunk = [&](int slot, int k) {
        const uint32_t base = sb + slot * STAGE3;
        const long koff = (long)k * 32;
#pragma unroll
        for (int mat = 0; mat < 3; ++mat) {
            const __half* g = mats[mat] + koff;
            const uint32_t mb = base + mat * MAT_BYTES;
            CP_ASYNC16(tile_addr(mb, r0a, c0a), g + (long)r0a * LL + c0a * 8);
            CP_ASYNC16(tile_addr(mb, r0b, c0a), g + (long)r0b * LL + c0a * 8);
        }
        CP_COMMIT();
    };

    float acc[2][8][4];
#pragma unroll
    for (int i = 0; i < 2; ++i)
#pragma unroll
        for (int j = 0; j < 8; ++j)
#pragma unroll
            for (int q = 0; q < 4; ++q) acc[i][j][q] = 0.0f;

    load_chunk(0, 0);
    load_chunk(1, 1);

#pragma unroll 1
    for (int k = 0; k < 32; ++k) {
        CP_WAIT(1);
        __syncthreads();
        if (k + 2 < 32) load_chunk((k + 2) % 3, k + 2);

        const uint32_t base = sb + (k % 3) * STAGE3;
        const uint32_t sP = base;
        const uint32_t sVh = base + MAT_BYTES, sVl = base + 2 * MAT_BYTES;

#pragma unroll
        for (int kg = 0; kg < 2; ++kg) {
            uint32_t a[2][4], bh[4][4], bl[4][4];
#pragma unroll
            for (int mt = 0; mt < 2; ++mt)
                ldsm4(a[mt], frag_addr(sP, warp_m * 32 + mt * 16, kg, lane));
#pragma unroll
            for (int ng = 0; ng < 4; ++ng) {
                ldsm4(bh[ng], frag_addr(sVh, warp_n * 64 + ng * 16, kg, lane));
                ldsm4(bl[ng], frag_addr(sVl, warp_n * 64 + ng * 16, kg, lane));
            }
#pragma unroll
            for (int mt = 0; mt < 2; ++mt)
#pragma unroll
                for (int ng = 0; ng < 4; ++ng)
#pragma unroll
                    for (int h = 0; h < 2; ++h) {
                        float* d = acc[mt][ng * 2 + h];
                        mma16816_f16(d, a[mt], bh[ng][h], bh[ng][h + 2]);
                        mma16816_f16(d, a[mt], bl[ng][h], bl[ng][h + 2]);
                    }
        }
    }
    __syncthreads();

    // epilogue: fp32 strided store into concat slot (ld 1536, +768 col offset)
    const int rbase = blockIdx.y * 128 + warp_m * 32 + (lane >> 2);
    const int cbase = blockIdx.x * 128 + warp_n * 64 + (lane & 3) * 2;
    float* Ob = out + (long)bz * LL * 1536 + DD;
#pragma unroll
    for (int mt = 0; mt < 2; ++mt)
#pragma unroll
        for (int nt = 0; nt < 8; ++nt) {
            const long r = rbase + mt * 16;
            const long c = cbase + nt * 8;
            float* Cp = Ob + r * 1536 + c;
            *(float2*)Cp = make_float2(acc[mt][nt][0], acc[mt][nt][1]);
            *(float2*)(Cp + 8L * 1536) = make_float2(acc[mt][nt][2], acc[mt][nt][3]);
        }
}

// ---------------------------------------------------------------------------
// split + transpose + passthrough
// ---------------------------------------------------------------------------
__global__ void split_tr(const float* __restrict__ X,
                         bf16* __restrict__ Xhi, bf16* __restrict__ Xlo,
                         __half* __restrict__ XTh, __half* __restrict__ XTl,
                         float* __restrict__ outbase)
{
    const int b = blockIdx.z;
    const int d0 = blockIdx.x * 32, l0 = blockIdx.y * 32;
    const int tx = threadIdx.x, ty = threadIdx.y;
    __shared__ __half thi[32][33], tlo[32][33];

#pragma unroll
    for (int i = 0; i < 4; ++i) {
        const int ll = ty + 8 * i;
        const size_t idx = (size_t)b * LL * DD + (size_t)(l0 + ll) * DD + d0 + tx;
        const float x = X[idx];
        const bf16 h = __float2bfloat16(x);
        Xhi[idx] = h;
        Xlo[idx] = __float2bfloat16(x - __bfloat162float(h));
        const __half fh = __float2half(x);
        thi[ll][tx] = fh;
        tlo[ll][tx] = __float2half(x - __half2float(fh));
        outbase[(size_t)(b * LL + l0 + ll) * 1536 + d0 + tx] = x;
    }
    __syncthreads();
#pragma unroll
    for (int i = 0; i < 4; ++i) {
        const int dd = ty + 8 * i;
        const size_t idx = (size_t)b * DD * LL + (size_t)(d0 + dd) * LL + l0 + tx;
        XTh[idx] = thi[tx][dd];
        XTl[idx] = tlo[tx][dd];
    }
}

__global__ void split_w(const float* __restrict__ Wl, const float* __restrict__ Wr,
                        bf16* __restrict__ Wlh, bf16* __restrict__ Wll,
                        bf16* __restrict__ Wrh, bf16* __restrict__ Wrl)
{
    const int i = blockIdx.x * blockDim.x + threadIdx.x;
    if (i < DD * DD) {
        float x = Wl[i];
        bf16 h = __float2bfloat16(x);
        Wlh[i] = h; Wll[i] = __float2bfloat16(x - __bfloat162float(h));
        x = Wr[i];
        h = __float2bfloat16(x);
        Wrh[i] = h; Wrl[i] = __float2bfloat16(x - __bfloat162float(h));
    }
}

// ---------------------------------------------------------------------------
// softmax stats
// ---------------------------------------------------------------------------
__global__ void row_stats(const float* __restrict__ S, float* __restrict__ rowc)
{
    const int row = blockIdx.x;
    const float* Sp = S + (size_t)row * LL;
    const int t = threadIdx.x;
    float v[4];
    float m = -1e30f;
#pragma unroll
    for (int i = 0; i < 4; ++i) { v[i] = Sp[t + i * 256]; m = fmaxf(m, v[i]); }
    __shared__ float red[256];
    red[t] = m; __syncthreads();
    for (int s = 128; s > 0; s >>= 1) {
        if (t < s) red[t] = fmaxf(red[t], red[t + s]);
        __syncthreads();
    }
    const float M = red[0];
    __syncthreads();
    float sum = 0.0f;
#pragma unroll
    for (int i = 0; i < 4; ++i) sum += __expf(v[i] - M);
    red[t] = sum; __syncthreads();
    for (int s = 128; s > 0; s >>= 1) {
        if (t < s) red[t] += red[t + s];
        __syncthreads();
    }
    if (t == 0) rowc[row] = M + __logf(red[0]);
}

__global__ void col_stats(const float* __restrict__ S, float* __restrict__ colc)
{
    const int b = blockIdx.y;
    const int tx = threadIdx.x, ty = threadIdx.y;
    const int c = blockIdx.x * 32 + tx;
    const float* Sp = S + (size_t)b * LL * LL + c;

    float m = -1e30f, s = 0.0f;
    for (int l = ty * 128; l < (ty + 1) * 128; ++l) {
        const float x = Sp[(size_t)l * LL] * INV_SCALE;
        if (x > m) { s = s * __expf(m - x) + 1.0f; m = x; }
        else s += __expf(x - m);
    }
    __shared__ float redm[8][32], reds[8][32];
    redm[ty][tx] = m; reds[ty][tx] = s;
    __syncthreads();
    if (ty == 0) {
        float M = redm[0][tx];
#pragma unroll
        for (int i = 1; i < 8; ++i) M = fmaxf(M, redm[i][tx]);
        float ss = 0.0f;
#pragma unroll
        for (int i = 0; i < 8; ++i) ss += reds[i][tx] * __expf(redm[i][tx] - M);
        colc[b * LL + c] = M + __logf(ss);
    }
}

// normalize into P1 fp16 [l][r] and P2T fp16 [r][l]
__global__ void transform(const float* __restrict__ S,
                          const float* __restrict__ rowc,
                          const float* __restrict__ colc,
                          __half* __restrict__ P1, __half* __restrict__ P2T)
{
    const int n = blockIdx.z;
    const size_t base = (size_t)n * LL * LL;
    const int l0 = blockIdx.y * 32, r0 = blockIdx.x * 32;
    const int tx = threadIdx.x, ty = threadIdx.y;
    __shared__ float tile[32][33];
    const float cc = colc[n * LL + r0 + tx];

#pragma unroll
    for (int i = 0; i < 4; ++i) {
        const int ll = ty + 8 * i;
        const size_t idx = base + (size_t)(l0 + ll) * LL + r0 + tx;
        const float s = S[idx];
        P1[idx] = __float2half(__expf(s - rowc[n * LL + l0 + ll]));
        tile[ll][tx] = s * INV_SCALE - cc;
    }
    __syncthreads();
#pragma unroll
    for (int i = 0; i < 4; ++i) {
        const int rr = ty + 8 * i;
        P2T[base + (size_t)(r0 + rr) * LL + l0 + tx] = __float2half(__expf(tile[tx][rr]));
    }
}

// ---------------------------------------------------------------------------
// launch
// ---------------------------------------------------------------------------
extern "C" void kernel_launch(void* const* d_in, const int* in_sizes, int n_in,
                              void* d_out, int out_size)
{
    const float* lhs = (const float*)d_in[0];
    const float* rhs = (const float*)d_in[1];
    const float* Wl  = (const float*)d_in[2];
    const float* Wr  = (const float*)d_in[3];
    float* out = (float*)d_out;

    bf16 *p_lhs_h, *p_lhs_l, *p_rhs_h, *p_rhs_l;
    __half *p_lhsT_h, *p_lhsT_l, *p_rhsT_h, *p_rhsT_l;
    bf16 *p_Wl_h, *p_Wl_l, *p_Wr_h, *p_Wr_l;
    bf16 *p_L_h, *p_L_l, *p_R_h, *p_R_l;
    __half *p_P1, *p_P2T;
    float *pS, *prc, *pcc;
    cudaGetSymbolAddress((void**)&p_lhs_h, s_lhs_hi);
    cudaGetSymbolAddress((void**)&p_lhs_l, s_lhs_lo);
    cudaGetSymbolAddress((void**)&p_rhs_h, s_rhs_hi);
    cudaGetSymbolAddress((void**)&p_rhs_l, s_rhs_lo);
    cudaGetSymbolAddress((void**)&p_lhsT_h, s_lhsT_h);
    cudaGetSymbolAddress((void**)&p_lhsT_l, s_lhsT_l);
    cudaGetSymbolAddress((void**)&p_rhsT_h, s_rhsT_h);
    cudaGetSymbolAddress((void**)&p_rhsT_l, s_rhsT_l);
    cudaGetSymbolAddress((void**)&p_Wl_h, s_Wl_hi);
    cudaGetSymbolAddress((void**)&p_Wl_l, s_Wl_lo);
    cudaGetSymbolAddress((void**)&p_Wr_h, s_Wr_hi);
    cudaGetSymbolAddress((void**)&p_Wr_l, s_Wr_lo);
    cudaGetSymbolAddress((void**)&p_L_h, g_L_hi);
    cudaGetSymbolAddress((void**)&p_L_l, g_L_lo);
    cudaGetSymbolAddress((void**)&p_R_h, g_R_hi);
    cudaGetSymbolAddress((void**)&p_R_l, g_R_lo);
    cudaGetSymbolAddress((void**)&p_P1, g_P1);
    cudaGetSymbolAddress((void**)&p_P2T, g_P2T);
    cudaGetSymbolAddress((void**)&pS, g_S);
    cudaGetSymbolAddress((void**)&prc, g_rowc);
    cudaGetSymbolAddress((void**)&pcc, g_colc);

    const int SMEM4 = 3 * STAGE4;  // 96 KB
    const int SMEM3 = 3 * STAGE3;  // 72 KB
    cudaFuncSetAttribute(mm_bf16x3<0>, cudaFuncAttributeMaxDynamicSharedMemorySize, SMEM4);
    cudaFuncSetAttribute(mm_bf16x3<1>, cudaFuncAttributeMaxDynamicSharedMemorySize, SMEM4);
    cudaFuncSetAttribute(mm_f16_apply, cudaFuncAttributeMaxDynamicSharedMemorySize, SMEM3);

    // 1. operand prep: split + transpose + passthrough copy
    split_tr<<<dim3(DD / 32, LL / 32, BB), dim3(32, 8)>>>(
        lhs, p_lhs_h, p_lhs_l, p_lhsT_h, p_lhsT_l, out);
    split_tr<<<dim3(DD / 32, LL / 32, BB), dim3(32, 8)>>>(
        rhs, p_rhs_h, p_rhs_l, p_rhsT_h, p_rhsT_l, out + (size_t)BB * LL * 1536);
    split_w<<<(DD * DD + 255) / 256, 256>>>(Wl, Wr, p_Wl_h, p_Wl_l, p_Wr_h, p_Wr_l);

    // 2. projections + tanh
    mm_bf16x3<1><<<dim3(DD / 128, (BB * LL) / 128, 1), 256, SMEM4>>>(
        p_lhs_h, p_lhs_l, p_Wl_h, p_Wl_l, 0, 0, DD, DD / 32,
        nullptr, 0, DD, p_L_h, p_L_l);
    mm_bf16x3<1><<<dim3(DD / 128, (BB * LL) / 128, 1), 256, SMEM4>>>(
        p_rhs_h, p_rhs_l, p_Wr_h, p_Wr_l, 0, 0, DD, DD / 32,
        nullptr, 0, DD, p_R_h, p_R_l);

    // 3. scores
    mm_bf16x3<0><<<dim3(LL / 128, LL / 128, BB), 256, SMEM4>>>(
        p_L_h, p_L_l, p_R_h, p_R_l,
        (long)LL * DD, (long)LL * DD, DD, DD / 32,
        pS, (long)LL * LL, LL, nullptr, nullptr);

    // 4. softmax stats + normalized fp16 probabilities
    row_stats<<<BB * LL, 256>>>(pS, prc);
    col_stats<<<dim3(LL / 32, BB), dim3(32, 8)>>>(pS, pcc);
    transform<<<dim3(LL / 32, LL / 32, BB), dim3(32, 8)>>>(pS, prc, pcc, p_P1, p_P2T);

    // 5. applies
    mm_f16_apply<<<dim3(DD / 128, LL / 128, BB), 256, SMEM3>>>(
        p_P1, p_rhsT_h, p_rhsT_l, out);
    mm_f16_apply<<<dim3(DD / 128, LL / 128, BB), 256, SMEM3>>>(
        p_P2T, p_lhsT_h, p_lhsT_l, out + (size_t)BB * LL * 1536);
}

// round 6
// speedup vs baseline: 3.5687x; 1.0237x over previous
#include <cuda_runtime.h>
#include <cuda_bf16.h>
#include <cuda_fp16.h>
#include <cstdint>
#include <math.h>

#define BB 8
#define LL 1024
#define DD 768
#define INV_SCALE 0.03608439182435161f  /* 1/sqrt(768) */

typedef __nv_bfloat16 bf16;

// ---------------------------------------------------------------------------
// scratch (device globals; no allocation)
// ---------------------------------------------------------------------------
__device__ bf16 s_lhs_hi[BB * LL * DD], s_lhs_lo[BB * LL * DD];   // proj A
__device__ bf16 s_rhs_hi[BB * LL * DD], s_rhs_lo[BB * LL * DD];
__device__ __half s_lhsT_h[BB * DD * LL], s_lhsT_l[BB * DD * LL]; // apply B (fp16)
__device__ __half s_rhsT_h[BB * DD * LL], s_rhsT_l[BB * DD * LL];
__device__ bf16 s_Wl_hi[DD * DD], s_Wl_lo[DD * DD];
__device__ bf16 s_Wr_hi[DD * DD], s_Wr_lo[DD * DD];
__device__ bf16 g_L_hi[BB * LL * DD], g_L_lo[BB * LL * DD];
__device__ bf16 g_R_hi[BB * LL * DD], g_R_lo[BB * LL * DD];
__device__ __half g_P1[BB * LL * LL];    // row-softmax probs fp16 [l][r]
__device__ __half g_P2T[BB * LL * LL];   // col-softmax probs fp16, transposed [r][l]
__device__ float g_S[BB * LL * LL];
__device__ float g_rowc[BB * LL];
__device__ float g_colc[BB * LL];

__device__ __forceinline__ float fast_tanh(float x) {
    return 1.0f - __fdividef(2.0f, __expf(2.0f * x) + 1.0f);
}

__device__ __forceinline__ uint32_t smem_to_u32(const void* p) {
    uint32_t a;
    asm("{ .reg .u64 t; cvta.to.shared.u64 t, %1; cvt.u32.u64 %0, t; }"
        : "=r"(a) : "l"(p));
    return a;
}

// ---------------------------------------------------------------------------
// HMMA helpers
// ---------------------------------------------------------------------------
__device__ __forceinline__ void ldsm4(uint32_t* r, uint32_t addr) {
    asm volatile("ldmatrix.sync.aligned.m8n8.x4.shared.b16 {%0,%1,%2,%3}, [%4];"
                 : "=r"(r[0]), "=r"(r[1]), "=r"(r[2]), "=r"(r[3]) : "r"(addr));
}

__device__ __forceinline__ void mma16816_bf(float* d, const uint32_t* a,
                                            uint32_t b0, uint32_t b1) {
    asm volatile(
        "mma.sync.aligned.m16n8k16.row.col.f32.bf16.bf16.f32 "
        "{%0,%1,%2,%3}, {%4,%5,%6,%7}, {%8,%9}, {%0,%1,%2,%3};"
        : "+f"(d[0]), "+f"(d[1]), "+f"(d[2]), "+f"(d[3])
        : "r"(a[0]), "r"(a[1]), "r"(a[2]), "r"(a[3]), "r"(b0), "r"(b1));
}

__device__ __forceinline__ void mma16816_f16(float* d, const uint32_t* a,
                                             uint32_t b0, uint32_t b1) {
    asm volatile(
        "mma.sync.aligned.m16n8k16.row.col.f32.f16.f16.f32 "
        "{%0,%1,%2,%3}, {%4,%5,%6,%7}, {%8,%9}, {%0,%1,%2,%3};"
        : "+f"(d[0]), "+f"(d[1]), "+f"(d[2]), "+f"(d[3])
        : "r"(a[0]), "r"(a[1]), "r"(a[2]), "r"(a[3]), "r"(b0), "r"(b1));
}

#define CP_ASYNC16(saddr, gptr) \
    asm volatile("cp.async.cg.shared.global [%0], [%1], 16;" \
        :: "r"(saddr), "l"(gptr) : "memory")
#define CP_COMMIT() asm volatile("cp.async.commit_group;" ::: "memory")
#define CP_WAIT(n) asm volatile("cp.async.wait_group %0;" :: "n"(n) : "memory")

// smem tile: 128 rows x 32 b16 (64B rows), swizzled 16B chunks
__device__ __forceinline__ uint32_t tile_addr(uint32_t matbase, int row, int chunk) {
    int swz = chunk ^ (row & 3) ^ ((row >> 2) & 1);
    return matbase + row * 64 + swz * 16;
}
__device__ __forceinline__ uint32_t frag_addr(uint32_t matbase, int baserow,
                                              int kg, int lane) {
    int row = baserow + (lane & 7) + ((lane >> 3) & 1) * 8;
    int chunk = kg * 2 + ((lane >> 4) & 1);
    return tile_addr(matbase, row, chunk);
}

#define MAT_BYTES 8192

// ---------------------------------------------------------------------------
// bf16x3 HMMA GEMM (proj + scores).  C = act((Ahi+Alo) @ (Bhi+Blo)^T)
// Block 128x128, 8 warps (4m x 2n), K-chunk 32, 3-stage cp.async pipeline.
// 2 CTAs/SM.  Term-outermost MMA order (no accumulator RAW chains).
// zsplit > 0: blocks with z >= zsplit use operand/output set 2 (merged launch).
// EPI 0: fp32 store.  EPI 1: tanh + split -> bf16 hi/lo.
// ---------------------------------------------------------------------------
#define STAGE4 32768  /* 4 matrices */

template <int EPI>
__global__ __launch_bounds__(256, 2) void mm_bf16x3(
    const bf16* __restrict__ Ahi, const bf16* __restrict__ Alo,
    const bf16* __restrict__ Bhi, const bf16* __restrict__ Blo,
    const bf16* __restrict__ A2hi, const bf16* __restrict__ A2lo,
    const bf16* __restrict__ B2hi, const bf16* __restrict__ B2lo,
    long sA, long sB, int ldk, int nch, int zsplit,
    float* __restrict__ C, long sC, int ldc,
    bf16* __restrict__ Chi, bf16* __restrict__ Clo,
    bf16* __restrict__ C2hi, bf16* __restrict__ C2lo)
{
    extern __shared__ char smem[];
    const uint32_t sb = smem_to_u32(smem);
    const int tid = threadIdx.x;
    const int lane = tid & 31;
    const int wid = tid >> 5;
    const int warp_m = wid & 3;
    const int warp_n = wid >> 2;

    int bz = blockIdx.z;
    const bf16 *pAh = Ahi, *pAl = Alo, *pBh = Bhi, *pBl = Blo;
    bf16 *pCh = Chi, *pCl = Clo;
    if (zsplit > 0 && bz >= zsplit) {
        bz -= zsplit;
        pAh = A2hi; pAl = A2lo; pBh = B2hi; pBl = B2lo;
        pCh = C2hi; pCl = C2lo;
    }

    const bf16* mats[4];
    mats[0] = pAh + (long)bz * sA + (long)blockIdx.y * 128 * ldk;
    mats[1] = pAl + (long)bz * sA + (long)blockIdx.y * 128 * ldk;
    mats[2] = pBh + (long)bz * sB + (long)blockIdx.x * 128 * ldk;
    mats[3] = pBl + (long)bz * sB + (long)blockIdx.x * 128 * ldk;

    const int r0a = tid >> 2, c0a = tid & 3;
    const int r0b = (tid + 256) >> 2;

    auto load_chunk = [&](int slot, int k) {
        const uint32_t base = sb + slot * STAGE4;
        const long koff = (long)k * 32;
#pragma unroll
        for (int mat = 0; mat < 4; ++mat) {
            const bf16* g = mats[mat] + koff;
            const uint32_t mb = base + mat * MAT_BYTES;
            CP_ASYNC16(tile_addr(mb, r0a, c0a), g + (long)r0a * ldk + c0a * 8);
            CP_ASYNC16(tile_addr(mb, r0b, c0a), g + (long)r0b * ldk + c0a * 8);
        }
        CP_COMMIT();
    };

    float acc[2][8][4];
#pragma unroll
    for (int i = 0; i < 2; ++i)
#pragma unroll
        for (int j = 0; j < 8; ++j)
#pragma unroll
            for (int q = 0; q < 4; ++q) acc[i][j][q] = 0.0f;

    load_chunk(0, 0);
    load_chunk(1, 1);

#pragma unroll 1
    for (int k = 0; k < nch; ++k) {
        CP_WAIT(1);
        __syncthreads();
        if (k + 2 < nch) load_chunk((k + 2) % 3, k + 2);

        const uint32_t base = sb + (k % 3) * STAGE4;
        const uint32_t sAh = base, sAl = base + MAT_BYTES;
        const uint32_t sBh = base + 2 * MAT_BYTES, sBl = base + 3 * MAT_BYTES;

#pragma unroll
        for (int kg = 0; kg < 2; ++kg) {
            uint32_t ah[2][4], al[2][4], bh[4][4], bl[4][4];
#pragma unroll
            for (int mt = 0; mt < 2; ++mt) {
                ldsm4(ah[mt], frag_addr(sAh, warp_m * 32 + mt * 16, kg, lane));
                ldsm4(al[mt], frag_addr(sAl, warp_m * 32 + mt * 16, kg, lane));
            }
#pragma unroll
            for (int ng = 0; ng < 4; ++ng) {
                ldsm4(bh[ng], frag_addr(sBh, warp_n * 64 + ng * 16, kg, lane));
                ldsm4(bl[ng], frag_addr(sBl, warp_n * 64 + ng * 16, kg, lane));
            }
            // term-outermost: each accumulator revisited only every 16 MMAs
#pragma unroll
            for (int term = 0; term < 3; ++term)
#pragma unroll
                for (int mt = 0; mt < 2; ++mt)
#pragma unroll
                    for (int ng = 0; ng < 4; ++ng)
#pragma unroll
                        for (int h = 0; h < 2; ++h) {
                            float* d = acc[mt][ng * 2 + h];
                            const uint32_t* a = (term == 2) ? al[mt] : ah[mt];
                            const uint32_t* b = (term == 1) ? bl[ng] : bh[ng];
                            mma16816_bf(d, a, b[h], b[h + 2]);
                        }
        }
    }
    __syncthreads();

    const int rbase = blockIdx.y * 128 + warp_m * 32 + (lane >> 2);
    const int cbase = blockIdx.x * 128 + warp_n * 64 + (lane & 3) * 2;

    if (EPI == 0) {
#pragma unroll
        for (int mt = 0; mt < 2; ++mt)
#pragma unroll
            for (int nt = 0; nt < 8; ++nt) {
                const long r = rbase + mt * 16;
                const long c = cbase + nt * 8;
                float* Cp = C + (long)bz * sC + r * ldc + c;
                *(float2*)Cp = make_float2(acc[mt][nt][0], acc[mt][nt][1]);
                *(float2*)(Cp + 8L * ldc) = make_float2(acc[mt][nt][2], acc[mt][nt][3]);
            }
    } else {
#pragma unroll
        for (int mt = 0; mt < 2; ++mt)
#pragma unroll
            for (int nt = 0; nt < 8; ++nt)
#pragma unroll
                for (int half = 0; half < 2; ++half) {
                    const long r = rbase + mt * 16 + half * 8;
                    const long c = cbase + nt * 8;
                    float v0 = fast_tanh(acc[mt][nt][half * 2 + 0]);
                    float v1 = fast_tanh(acc[mt][nt][half * 2 + 1]);
                    bf16 h0 = __float2bfloat16(v0);
                    bf16 h1 = __float2bfloat16(v1);
                    bf16 l0 = __float2bfloat16(v0 - __bfloat162float(h0));
                    bf16 l1 = __float2bfloat16(v1 - __bfloat162float(h1));
                    __nv_bfloat162 hh; hh.x = h0; hh.y = h1;
                    __nv_bfloat162 llv; llv.x = l0; llv.y = l1;
                    *(uint32_t*)(pCh + r * ldc + c) = *(uint32_t*)&hh;
                    *(uint32_t*)(pCl + r * ldc + c) = *(uint32_t*)&llv;
                }
    }
}

// ---------------------------------------------------------------------------
// fp16 asym-2 apply GEMM (merged both directions): out = P @ (Vhi+Vlo)^T
// grid z in [0,16): dir = z>>3, batch = z&7.
// ---------------------------------------------------------------------------
#define STAGE3 24576  /* 3 matrices */

__global__ __launch_bounds__(256, 2) void mm_f16_apply(
    const __half* __restrict__ P1,
    const __half* __restrict__ V1hi, const __half* __restrict__ V1lo,
    float* __restrict__ out1,
    const __half* __restrict__ P2,
    const __half* __restrict__ V2hi, const __half* __restrict__ V2lo,
    float* __restrict__ out2)
{
    extern __shared__ char smem[];
    const uint32_t sb = smem_to_u32(smem);
    const int tid = threadIdx.x;
    const int lane = tid & 31;
    const int wid = tid >> 5;
    const int warp_m = wid & 3;
    const int warp_n = wid >> 2;

    const int bz = blockIdx.z & 7;
    const int dir = blockIdx.z >> 3;
    const __half* P = dir ? P2 : P1;
    const __half* Vhi = dir ? V2hi : V1hi;
    const __half* Vlo = dir ? V2lo : V1lo;
    float* out = dir ? out2 : out1;

    const __half* mats[3];
    mats[0] = P + (long)bz * LL * LL + (long)blockIdx.y * 128 * LL;
    mats[1] = Vhi + (long)bz * DD * LL + (long)blockIdx.x * 128 * LL;
    mats[2] = Vlo + (long)bz * DD * LL + (long)blockIdx.x * 128 * LL;

    const int r0a = tid >> 2, c0a = tid & 3;
    const int r0b = (tid + 256) >> 2;

    auto load_chunk = [&](int slot, int k) {
        const uint32_t base = sb + slot * STAGE3;
        const long koff = (long)k * 32;
#pragma unroll
        for (int mat = 0; mat < 3; ++mat) {
            const __half* g = mats[mat] + koff;
            const uint32_t mb = base + mat * MAT_BYTES;
            CP_ASYNC16(tile_addr(mb, r0a, c0a), g + (long)r0a * LL + c0a * 8);
            CP_ASYNC16(tile_addr(mb, r0b, c0a), g + (long)r0b * LL + c0a * 8);
        }
        CP_COMMIT();
    };

    float acc[2][8][4];
#pragma unroll
    for (int i = 0; i < 2; ++i)
#pragma unroll
        for (int j = 0; j < 8; ++j)
#pragma unroll
            for (int q = 0; q < 4; ++q) acc[i][j][q] = 0.0f;

    load_chunk(0, 0);
    load_chunk(1, 1);

#pragma unroll 1
    for (int k = 0; k < 32; ++k) {
        CP_WAIT(1);
        __syncthreads();
        if (k + 2 < 32) load_chunk((k + 2) % 3, k + 2);

        const uint32_t base = sb + (k % 3) * STAGE3;
        const uint32_t sP = base;
        const uint32_t sVh = base + MAT_BYTES, sVl = base + 2 * MAT_BYTES;

#pragma unroll
        for (int kg = 0; kg < 2; ++kg) {
            uint32_t a[2][4], bh[4][4], bl[4][4];
#pragma unroll
            for (int mt = 0; mt < 2; ++mt)
                ldsm4(a[mt], frag_addr(sP, warp_m * 32 + mt * 16, kg, lane));
#pragma unroll
            for (int ng = 0; ng < 4; ++ng) {
                ldsm4(bh[ng], frag_addr(sVh, warp_n * 64 + ng * 16, kg, lane));
                ldsm4(bl[ng], frag_addr(sVl, warp_n * 64 + ng * 16, kg, lane));
            }
#pragma unroll
            for (int term = 0; term < 2; ++term)
#pragma unroll
                for (int mt = 0; mt < 2; ++mt)
#pragma unroll
                    for (int ng = 0; ng < 4; ++ng)
#pragma unroll
                        for (int h = 0; h < 2; ++h) {
                            float* d = acc[mt][ng * 2 + h];
                            const uint32_t* b = term ? bl[ng] : bh[ng];
                            mma16816_f16(d, a[mt], b[h], b[h + 2]);
                        }
        }
    }
    __syncthreads();

    const int rbase = blockIdx.y * 128 + warp_m * 32 + (lane >> 2);
    const int cbase = blockIdx.x * 128 + warp_n * 64 + (lane & 3) * 2;
    float* Ob = out + (long)bz * LL * 1536 + DD;
#pragma unroll
    for (int mt = 0; mt < 2; ++mt)
#pragma unroll
        for (int nt = 0; nt < 8; ++nt) {
            const long r = rbase + mt * 16;
            const long c = cbase + nt * 8;
            float* Cp = Ob + r * 1536 + c;
            *(float2*)Cp = make_float2(acc[mt][nt][0], acc[mt][nt][1]);
            *(float2*)(Cp + 8L * 1536) = make_float2(acc[mt][nt][2], acc[mt][nt][3]);
        }
}

// ---------------------------------------------------------------------------
// split + transpose + passthrough
// ---------------------------------------------------------------------------
__global__ void split_tr(const float* __restrict__ X,
                         bf16* __restrict__ Xhi, bf16* __restrict__ Xlo,
                         __half* __restrict__ XTh, __half* __restrict__ XTl,
                         float* __restrict__ outbase)
{
    const int b = blockIdx.z;
    const int d0 = blockIdx.x * 32, l0 = blockIdx.y * 32;
    const int tx = threadIdx.x, ty = threadIdx.y;
    __shared__ __half thi[32][33], tlo[32][33];

#pragma unroll
    for (int i = 0; i < 4; ++i) {
        const int ll = ty + 8 * i;
        const size_t idx = (size_t)b * LL * DD + (size_t)(l0 + ll) * DD + d0 + tx;
        const float x = X[idx];
        const bf16 h = __float2bfloat16(x);
        Xhi[idx] = h;
        Xlo[idx] = __float2bfloat16(x - __bfloat162float(h));
        const __half fh = __float2half(x);
        thi[ll][tx] = fh;
        tlo[ll][tx] = __float2half(x - __half2float(fh));
        outbase[(size_t)(b * LL + l0 + ll) * 1536 + d0 + tx] = x;
    }
    __syncthreads();
#pragma unroll
    for (int i = 0; i < 4; ++i) {
        const int dd = ty + 8 * i;
        const size_t idx = (size_t)b * DD * LL + (size_t)(d0 + dd) * LL + l0 + tx;
        XTh[idx] = thi[tx][dd];
        XTl[idx] = tlo[tx][dd];
    }
}

__global__ void split_w(const float* __restrict__ Wl, const float* __restrict__ Wr,
                        bf16* __restrict__ Wlh, bf16* __restrict__ Wll,
                        bf16* __restrict__ Wrh, bf16* __restrict__ Wrl)
{
    const int i = blockIdx.x * blockDim.x + threadIdx.x;
    if (i < DD * DD) {
        float x = Wl[i];
        bf16 h = __float2bfloat16(x);
        Wlh[i] = h; Wll[i] = __float2bfloat16(x - __bfloat162float(h));
        x = Wr[i];
        h = __float2bfloat16(x);
        Wrh[i] = h; Wrl[i] = __float2bfloat16(x - __bfloat162float(h));
    }
}

// ---------------------------------------------------------------------------
// softmax stats
// ---------------------------------------------------------------------------
__global__ void row_stats(const float* __restrict__ S, float* __restrict__ rowc)
{
    const int row = blockIdx.x;
    const float* Sp = S + (size_t)row * LL;
    const int t = threadIdx.x;
    float v[4];
    float m = -1e30f;
#pragma unroll
    for (int i = 0; i < 4; ++i) { v[i] = Sp[t + i * 256]; m = fmaxf(m, v[i]); }
    __shared__ float red[256];
    red[t] = m; __syncthreads();
    for (int s = 128; s > 0; s >>= 1) {
        if (t < s) red[t] = fmaxf(red[t], red[t + s]);
        __syncthreads();
    }
    const float M = red[0];
    __syncthreads();
    float sum = 0.0f;
#pragma unroll
    for (int i = 0; i < 4; ++i) sum += __expf(v[i] - M);
    red[t] = sum; __syncthreads();
    for (int s = 128; s > 0; s >>= 1) {
        if (t < s) red[t] += red[t + s];
        __syncthreads();
    }
    if (t == 0) rowc[row] = M + __logf(red[0]);
}

__global__ void col_stats(const float* __restrict__ S, float* __restrict__ colc)
{
    const int b = blockIdx.y;
    const int tx = threadIdx.x, ty = threadIdx.y;
    const int c = blockIdx.x * 32 + tx;
    const float* Sp = S + (size_t)b * LL * LL + c;

    float m = -1e30f, s = 0.0f;
    for (int l = ty * 128; l < (ty + 1) * 128; ++l) {
        const float x = Sp[(size_t)l * LL] * INV_SCALE;
        if (x > m) { s = s * __expf(m - x) + 1.0f; m = x; }
        else s += __expf(x - m);
    }
    __shared__ float redm[8][32], reds[8][32];
    redm[ty][tx] = m; reds[ty][tx] = s;
    __syncthreads();
    if (ty == 0) {
        float M = redm[0][tx];
#pragma unroll
        for (int i = 1; i < 8; ++i) M = fmaxf(M, redm[i][tx]);
        float ss = 0.0f;
#pragma unroll
        for (int i = 0; i < 8; ++i) ss += reds[i][tx] * __expf(redm[i][tx] - M);
        colc[b * LL + c] = M + __logf(ss);
    }
}

// normalize into P1 fp16 [l][r] and P2T fp16 [r][l]
__global__ void transform(const float* __restrict__ S,
                          const float* __restrict__ rowc,
                          const float* __restrict__ colc,
                          __half* __restrict__ P1, __half* __restrict__ P2T)
{
    const int n = blockIdx.z;
    const size_t base = (size_t)n * LL * LL;
    const int l0 = blockIdx.y * 32, r0 = blockIdx.x * 32;
    const int tx = threadIdx.x, ty = threadIdx.y;
    __shared__ float tile[32][33];
    const float cc = colc[n * LL + r0 + tx];

#pragma unroll
    for (int i = 0; i < 4; ++i) {
        const int ll = ty + 8 * i;
        const size_t idx = base + (size_t)(l0 + ll) * LL + r0 + tx;
        const float s = S[idx];
        P1[idx] = __float2half(__expf(s - rowc[n * LL + l0 + ll]));
        tile[ll][tx] = s * INV_SCALE - cc;
    }
    __syncthreads();
#pragma unroll
    for (int i = 0; i < 4; ++i) {
        const int rr = ty + 8 * i;
        P2T[base + (size_t)(r0 + rr) * LL + l0 + tx] = __float2half(__expf(tile[tx][rr]));
    }
}

// ---------------------------------------------------------------------------
// launch
// ---------------------------------------------------------------------------
extern "C" void kernel_launch(void* const* d_in, const int* in_sizes, int n_in,
                              void* d_out, int out_size)
{
    const float* lhs = (const float*)d_in[0];
    const float* rhs = (const float*)d_in[1];
    const float* Wl  = (const float*)d_in[2];
    const float* Wr  = (const float*)d_in[3];
    float* out = (float*)d_out;

    bf16 *p_lhs_h, *p_lhs_l, *p_rhs_h, *p_rhs_l;
    __half *p_lhsT_h, *p_lhsT_l, *p_rhsT_h, *p_rhsT_l;
    bf16 *p_Wl_h, *p_Wl_l, *p_Wr_h, *p_Wr_l;
    bf16 *p_L_h, *p_L_l, *p_R_h, *p_R_l;
    __half *p_P1, *p_P2T;
    float *pS, *prc, *pcc;
    cudaGetSymbolAddress((void**)&p_lhs_h, s_lhs_hi);
    cudaGetSymbolAddress((void**)&p_lhs_l, s_lhs_lo);
    cudaGetSymbolAddress((void**)&p_rhs_h, s_rhs_hi);
    cudaGetSymbolAddress((void**)&p_rhs_l, s_rhs_lo);
    cudaGetSymbolAddress((void**)&p_lhsT_h, s_lhsT_h);
    cudaGetSymbolAddress((void**)&p_lhsT_l, s_lhsT_l);
    cudaGetSymbolAddress((void**)&p_rhsT_h, s_rhsT_h);
    cudaGetSymbolAddress((void**)&p_rhsT_l, s_rhsT_l);
    cudaGetSymbolAddress((void**)&p_Wl_h, s_Wl_hi);
    cudaGetSymbolAddress((void**)&p_Wl_l, s_Wl_lo);
    cudaGetSymbolAddress((void**)&p_Wr_h, s_Wr_hi);
    cudaGetSymbolAddress((void**)&p_Wr_l, s_Wr_lo);
    cudaGetSymbolAddress((void**)&p_L_h, g_L_hi);
    cudaGetSymbolAddress((void**)&p_L_l, g_L_lo);
    cudaGetSymbolAddress((void**)&p_R_h, g_R_hi);
    cudaGetSymbolAddress((void**)&p_R_l, g_R_lo);
    cudaGetSymbolAddress((void**)&p_P1, g_P1);
    cudaGetSymbolAddress((void**)&p_P2T, g_P2T);
    cudaGetSymbolAddress((void**)&pS, g_S);
    cudaGetSymbolAddress((void**)&prc, g_rowc);
    cudaGetSymbolAddress((void**)&pcc, g_colc);

    const int SMEM4 = 3 * STAGE4;  // 96 KB
    const int SMEM3 = 3 * STAGE3;  // 72 KB
    cudaFuncSetAttribute(mm_bf16x3<0>, cudaFuncAttributeMaxDynamicSharedMemorySize, SMEM4);
    cudaFuncSetAttribute(mm_bf16x3<1>, cudaFuncAttributeMaxDynamicSharedMemorySize, SMEM4);
    cudaFuncSetAttribute(mm_f16_apply, cudaFuncAttributeMaxDynamicSharedMemorySize, SMEM3);

    // 1. operand prep: split + transpose + passthrough copy
    split_tr<<<dim3(DD / 32, LL / 32, BB), dim3(32, 8)>>>(
        lhs, p_lhs_h, p_lhs_l, p_lhsT_h, p_lhsT_l, out);
    split_tr<<<dim3(DD / 32, LL / 32, BB), dim3(32, 8)>>>(
        rhs, p_rhs_h, p_rhs_l, p_rhsT_h, p_rhsT_l, out + (size_t)BB * LL * 1536);
    split_w<<<(DD * DD + 255) / 256, 256>>>(Wl, Wr, p_Wl_h, p_Wl_l, p_Wr_h, p_Wr_l);

    // 2. both projections in ONE launch (z=0: lhs@Wl, z=1: rhs@Wr)
    mm_bf16x3<1><<<dim3(DD / 128, (BB * LL) / 128, 2), 256, SMEM4>>>(
        p_lhs_h, p_lhs_l, p_Wl_h, p_Wl_l,
        p_rhs_h, p_rhs_l, p_Wr_h, p_Wr_l,
        0, 0, DD, DD / 32, 1,
        nullptr, 0, DD, p_L_h, p_L_l, p_R_h, p_R_l);

    // 3. scores
    mm_bf16x3<0><<<dim3(LL / 128, LL / 128, BB), 256, SMEM4>>>(
        p_L_h, p_L_l, p_R_h, p_R_l,
        nullptr, nullptr, nullptr, nullptr,
        (long)LL * DD, (long)LL * DD, DD, DD / 32, 0,
        pS, (long)LL * LL, LL, nullptr, nullptr, nullptr, nullptr);

    // 4. softmax stats + normalized fp16 probabilities
    row_stats<<<BB * LL, 256>>>(pS, prc);
    col_stats<<<dim3(LL / 32, BB), dim3(32, 8)>>>(pS, pcc);
    transform<<<dim3(LL / 32, LL / 32, BB), dim3(32, 8)>>>(pS, prc, pcc, p_P1, p_P2T);

    // 5. both applies in ONE launch (z<8: dir 0, z>=8: dir 1)
    mm_f16_apply<<<dim3(DD / 128, LL / 128, 2 * BB), 256, SMEM3>>>(
        p_P1, p_rhsT_h, p_rhsT_l, out,
        p_P2T, p_lhsT_h, p_lhsT_l, out + (size_t)BB * LL * 1536);
}

// round 7
// speedup vs baseline: 4.1413x; 1.1605x over previous
#include <cuda_runtime.h>
#include <cuda_bf16.h>
#include <cuda_fp16.h>
#include <cstdint>
#include <math.h>

#define BB 8
#define LL 1024
#define DD 768
#define INV_SCALE 0.03608439182435161f  /* 1/sqrt(768) */

typedef __nv_bfloat16 bf16;

// ---------------------------------------------------------------------------
// scratch (device globals; no allocation)
// ---------------------------------------------------------------------------
__device__ bf16 s_lhs_hi[BB * LL * DD], s_lhs_lo[BB * LL * DD];   // proj A
__device__ bf16 s_rhs_hi[BB * LL * DD], s_rhs_lo[BB * LL * DD];
__device__ __half s_lhsT_h[BB * DD * LL];   // apply B (fp16, single)
__device__ __half s_rhsT_h[BB * DD * LL];
__device__ bf16 s_Wl_hi[DD * DD], s_Wl_lo[DD * DD];
__device__ bf16 s_Wr_hi[DD * DD], s_Wr_lo[DD * DD];
__device__ bf16 g_L_hi[BB * LL * DD], g_L_lo[BB * LL * DD];
__device__ bf16 g_R_hi[BB * LL * DD], g_R_lo[BB * LL * DD];
__device__ __half g_P1[BB * LL * LL];    // row-softmax probs fp16 [l][r]
__device__ __half g_P2T[BB * LL * LL];   // col-softmax probs fp16, transposed [r][l]
__device__ float g_S[BB * LL * LL];
__device__ float g_rowc[BB * LL];
__device__ float g_colc[BB * LL];

__device__ __forceinline__ float fast_tanh(float x) {
    return 1.0f - __fdividef(2.0f, __expf(2.0f * x) + 1.0f);
}

__device__ __forceinline__ uint32_t smem_to_u32(const void* p) {
    uint32_t a;
    asm("{ .reg .u64 t; cvta.to.shared.u64 t, %1; cvt.u32.u64 %0, t; }"
        : "=r"(a) : "l"(p));
    return a;
}

// ---------------------------------------------------------------------------
// HMMA helpers
// ---------------------------------------------------------------------------
__device__ __forceinline__ void ldsm4(uint32_t* r, uint32_t addr) {
    asm volatile("ldmatrix.sync.aligned.m8n8.x4.shared.b16 {%0,%1,%2,%3}, [%4];"
                 : "=r"(r[0]), "=r"(r[1]), "=r"(r[2]), "=r"(r[3]) : "r"(addr));
}

__device__ __forceinline__ void mma16816_bf(float* d, const uint32_t* a,
                                            uint32_t b0, uint32_t b1) {
    asm volatile(
        "mma.sync.aligned.m16n8k16.row.col.f32.bf16.bf16.f32 "
        "{%0,%1,%2,%3}, {%4,%5,%6,%7}, {%8,%9}, {%0,%1,%2,%3};"
        : "+f"(d[0]), "+f"(d[1]), "+f"(d[2]), "+f"(d[3])
        : "r"(a[0]), "r"(a[1]), "r"(a[2]), "r"(a[3]), "r"(b0), "r"(b1));
}

__device__ __forceinline__ void mma16816_f16(float* d, const uint32_t* a,
                                             uint32_t b0, uint32_t b1) {
    asm volatile(
        "mma.sync.aligned.m16n8k16.row.col.f32.f16.f16.f32 "
        "{%0,%1,%2,%3}, {%4,%5,%6,%7}, {%8,%9}, {%0,%1,%2,%3};"
        : "+f"(d[0]), "+f"(d[1]), "+f"(d[2]), "+f"(d[3])
        : "r"(a[0]), "r"(a[1]), "r"(a[2]), "r"(a[3]), "r"(b0), "r"(b1));
}

#define CP_ASYNC16(saddr, gptr) \
    asm volatile("cp.async.cg.shared.global [%0], [%1], 16;" \
        :: "r"(saddr), "l"(gptr) : "memory")
#define CP_COMMIT() asm volatile("cp.async.commit_group;" ::: "memory")
#define CP_WAIT(n) asm volatile("cp.async.wait_group %0;" :: "n"(n) : "memory")

// 64B-row tile (K-chunk 32): swizzled 16B chunks
__device__ __forceinline__ uint32_t tile_addr(uint32_t matbase, int row, int chunk) {
    int swz = chunk ^ (row & 3) ^ ((row >> 2) & 1);
    return matbase + row * 64 + swz * 16;
}
__device__ __forceinline__ uint32_t frag_addr(uint32_t matbase, int baserow,
                                              int kg, int lane) {
    int row = baserow + (lane & 7) + ((lane >> 3) & 1) * 8;
    int chunk = kg * 2 + ((lane >> 4) & 1);
    return tile_addr(matbase, row, chunk);
}

// 128B-row tile (K-chunk 64): swizzled 16B chunks, 8 per row
__device__ __forceinline__ uint32_t tile2_addr(uint32_t matbase, int row, int chunk) {
    int swz = chunk ^ (row & 7);
    return matbase + row * 128 + swz * 16;
}
__device__ __forceinline__ uint32_t frag2_addr(uint32_t matbase, int baserow,
                                               int kg, int lane) {
    int row = baserow + (lane & 7) + ((lane >> 3) & 1) * 8;
    int chunk = kg * 2 + ((lane >> 4) & 1);
    return tile2_addr(matbase, row, chunk);
}

#define MAT_BYTES 8192

// ---------------------------------------------------------------------------
// bf16x3 HMMA GEMM (proj + scores).  C = act((Ahi+Alo) @ (Bhi+Blo)^T)
// Block 128x128, 8 warps (4m x 2n), K-chunk 32, 3-stage cp.async, 2 CTAs/SM.
// ---------------------------------------------------------------------------
#define STAGE4 32768  /* 4 matrices x 8 KB */

template <int EPI>
__global__ __launch_bounds__(256, 2) void mm_bf16x3(
    const bf16* __restrict__ Ahi, const bf16* __restrict__ Alo,
    const bf16* __restrict__ Bhi, const bf16* __restrict__ Blo,
    const bf16* __restrict__ A2hi, const bf16* __restrict__ A2lo,
    const bf16* __restrict__ B2hi, const bf16* __restrict__ B2lo,
    long sA, long sB, int ldk, int nch, int zsplit,
    float* __restrict__ C, long sC, int ldc,
    bf16* __restrict__ Chi, bf16* __restrict__ Clo,
    bf16* __restrict__ C2hi, bf16* __restrict__ C2lo)
{
    extern __shared__ char smem[];
    const uint32_t sb = smem_to_u32(smem);
    const int tid = threadIdx.x;
    const int lane = tid & 31;
    const int wid = tid >> 5;
    const int warp_m = wid & 3;
    const int warp_n = wid >> 2;

    int bz = blockIdx.z;
    const bf16 *pAh = Ahi, *pAl = Alo, *pBh = Bhi, *pBl = Blo;
    bf16 *pCh = Chi, *pCl = Clo;
    if (zsplit > 0 && bz >= zsplit) {
        bz -= zsplit;
        pAh = A2hi; pAl = A2lo; pBh = B2hi; pBl = B2lo;
        pCh = C2hi; pCl = C2lo;
    }

    const bf16* mats[4];
    mats[0] = pAh + (long)bz * sA + (long)blockIdx.y * 128 * ldk;
    mats[1] = pAl + (long)bz * sA + (long)blockIdx.y * 128 * ldk;
    mats[2] = pBh + (long)bz * sB + (long)blockIdx.x * 128 * ldk;
    mats[3] = pBl + (long)bz * sB + (long)blockIdx.x * 128 * ldk;

    const int r0a = tid >> 2, c0a = tid & 3;
    const int r0b = (tid + 256) >> 2;

    auto load_chunk = [&](int slot, int k) {
        const uint32_t base = sb + slot * STAGE4;
        const long koff = (long)k * 32;
#pragma unroll
        for (int mat = 0; mat < 4; ++mat) {
            const bf16* g = mats[mat] + koff;
            const uint32_t mb = base + mat * MAT_BYTES;
            CP_ASYNC16(tile_addr(mb, r0a, c0a), g + (long)r0a * ldk + c0a * 8);
            CP_ASYNC16(tile_addr(mb, r0b, c0a), g + (long)r0b * ldk + c0a * 8);
        }
        CP_COMMIT();
    };

    float acc[2][8][4];
#pragma unroll
    for (int i = 0; i < 2; ++i)
#pragma unroll
        for (int j = 0; j < 8; ++j)
#pragma unroll
            for (int q = 0; q < 4; ++q) acc[i][j][q] = 0.0f;

    load_chunk(0, 0);
    load_chunk(1, 1);

#pragma unroll 1
    for (int k = 0; k < nch; ++k) {
        CP_WAIT(1);
        __syncthreads();
        if (k + 2 < nch) load_chunk((k + 2) % 3, k + 2);

        const uint32_t base = sb + (k % 3) * STAGE4;
        const uint32_t sAh = base, sAl = base + MAT_BYTES;
        const uint32_t sBh = base + 2 * MAT_BYTES, sBl = base + 3 * MAT_BYTES;

#pragma unroll
        for (int kg = 0; kg < 2; ++kg) {
            uint32_t ah[2][4], al[2][4], bh[4][4], bl[4][4];
#pragma unroll
            for (int mt = 0; mt < 2; ++mt) {
                ldsm4(ah[mt], frag_addr(sAh, warp_m * 32 + mt * 16, kg, lane));
                ldsm4(al[mt], frag_addr(sAl, warp_m * 32 + mt * 16, kg, lane));
            }
#pragma unroll
            for (int ng = 0; ng < 4; ++ng) {
                ldsm4(bh[ng], frag_addr(sBh, warp_n * 64 + ng * 16, kg, lane));
                ldsm4(bl[ng], frag_addr(sBl, warp_n * 64 + ng * 16, kg, lane));
            }
#pragma unroll
            for (int term = 0; term < 3; ++term)
#pragma unroll
                for (int mt = 0; mt < 2; ++mt)
#pragma unroll
                    for (int ng = 0; ng < 4; ++ng)
#pragma unroll
                        for (int h = 0; h < 2; ++h) {
                            float* d = acc[mt][ng * 2 + h];
                            const uint32_t* a = (term == 2) ? al[mt] : ah[mt];
                            const uint32_t* b = (term == 1) ? bl[ng] : bh[ng];
                            mma16816_bf(d, a, b[h], b[h + 2]);
                        }
        }
    }
    __syncthreads();

    const int rbase = blockIdx.y * 128 + warp_m * 32 + (lane >> 2);
    const int cbase = blockIdx.x * 128 + warp_n * 64 + (lane & 3) * 2;

    if (EPI == 0) {
#pragma unroll
        for (int mt = 0; mt < 2; ++mt)
#pragma unroll
            for (int nt = 0; nt < 8; ++nt) {
                const long r = rbase + mt * 16;
                const long c = cbase + nt * 8;
                float* Cp = C + (long)bz * sC + r * ldc + c;
                *(float2*)Cp = make_float2(acc[mt][nt][0], acc[mt][nt][1]);
                *(float2*)(Cp + 8L * ldc) = make_float2(acc[mt][nt][2], acc[mt][nt][3]);
            }
    } else {
#pragma unroll
        for (int mt = 0; mt < 2; ++mt)
#pragma unroll
            for (int nt = 0; nt < 8; ++nt)
#pragma unroll
                for (int half = 0; half < 2; ++half) {
                    const long r = rbase + mt * 16 + half * 8;
                    const long c = cbase + nt * 8;
                    float v0 = fast_tanh(acc[mt][nt][half * 2 + 0]);
                    float v1 = fast_tanh(acc[mt][nt][half * 2 + 1]);
                    bf16 h0 = __float2bfloat16(v0);
                    bf16 h1 = __float2bfloat16(v1);
                    bf16 l0 = __float2bfloat16(v0 - __bfloat162float(h0));
                    bf16 l1 = __float2bfloat16(v1 - __bfloat162float(h1));
                    __nv_bfloat162 hh; hh.x = h0; hh.y = h1;
                    __nv_bfloat162 llv; llv.x = l0; llv.y = l1;
                    *(uint32_t*)(pCh + r * ldc + c) = *(uint32_t*)&hh;
                    *(uint32_t*)(pCl + r * ldc + c) = *(uint32_t*)&llv;
                }
    }
}

// ---------------------------------------------------------------------------
// fp16 single-V apply GEMM (both dirs merged): out = P @ V^T
// P: M x K fp16, V: N x K fp16.  K-chunk 64 (128B rows), 3 stages, 2 CTAs/SM.
// grid z in [0,16): dir = z>>3, batch = z&7.
// ---------------------------------------------------------------------------
#define MAT2_BYTES 16384
#define STAGEA 32768  /* 2 matrices x 16 KB */

__global__ __launch_bounds__(256, 2) void mm_f16_apply(
    const __half* __restrict__ P1, const __half* __restrict__ V1,
    float* __restrict__ out1,
    const __half* __restrict__ P2, const __half* __restrict__ V2,
    float* __restrict__ out2)
{
    extern __shared__ char smem[];
    const uint32_t sb = smem_to_u32(smem);
    const int tid = threadIdx.x;
    const int lane = tid & 31;
    const int wid = tid >> 5;
    const int warp_m = wid & 3;
    const int warp_n = wid >> 2;

    const int bz = blockIdx.z & 7;
    const int dir = blockIdx.z >> 3;
    const __half* P = dir ? P2 : P1;
    const __half* V = dir ? V2 : V1;
    float* out = dir ? out2 : out1;

    const __half* mats[2];
    mats[0] = P + (long)bz * LL * LL + (long)blockIdx.y * 128 * LL;
    mats[1] = V + (long)bz * DD * LL + (long)blockIdx.x * 128 * LL;

    const int rr0 = tid >> 3, cc0 = tid & 7;   // 128 rows x 8 chunks, 4 passes

    auto load_chunk = [&](int slot, int k) {
        const uint32_t base = sb + slot * STAGEA;
        const long koff = (long)k * 64;
#pragma unroll
        for (int mat = 0; mat < 2; ++mat) {
            const __half* g = mats[mat] + koff;
            const uint32_t mb = base + mat * MAT2_BYTES;
#pragma unroll
            for (int i = 0; i < 4; ++i) {
                const int row = rr0 + i * 32;
                CP_ASYNC16(tile2_addr(mb, row, cc0), g + (long)row * LL + cc0 * 8);
            }
        }
        CP_COMMIT();
    };

    float acc[2][8][4];
#pragma unroll
    for (int i = 0; i < 2; ++i)
#pragma unroll
        for (int j = 0; j < 8; ++j)
#pragma unroll
            for (int q = 0; q < 4; ++q) acc[i][j][q] = 0.0f;

    load_chunk(0, 0);
    load_chunk(1, 1);

#pragma unroll 1
    for (int k = 0; k < 16; ++k) {   // 16 chunks of K=64 -> 1024
        CP_WAIT(1);
        __syncthreads();
        if (k + 2 < 16) load_chunk((k + 2) % 3, k + 2);

        const uint32_t base = sb + (k % 3) * STAGEA;
        const uint32_t sP = base;
        const uint32_t sV = base + MAT2_BYTES;

#pragma unroll
        for (int kg = 0; kg < 4; ++kg) {
            uint32_t a[2][4], b[4][4];
#pragma unroll
            for (int mt = 0; mt < 2; ++mt)
                ldsm4(a[mt], frag2_addr(sP, warp_m * 32 + mt * 16, kg, lane));
#pragma unroll
            for (int ng = 0; ng < 4; ++ng)
                ldsm4(b[ng], frag2_addr(sV, warp_n * 64 + ng * 16, kg, lane));
#pragma unroll
            for (int mt = 0; mt < 2; ++mt)
#pragma unroll
                for (int ng = 0; ng < 4; ++ng)
#pragma unroll
                    for (int h = 0; h < 2; ++h)
                        mma16816_f16(acc[mt][ng * 2 + h], a[mt],
                                     b[ng][h], b[ng][h + 2]);
        }
    }
    __syncthreads();

    const int rbase = blockIdx.y * 128 + warp_m * 32 + (lane >> 2);
    const int cbase = blockIdx.x * 128 + warp_n * 64 + (lane & 3) * 2;
    float* Ob = out + (long)bz * LL * 1536 + DD;
#pragma unroll
    for (int mt = 0; mt < 2; ++mt)
#pragma unroll
        for (int nt = 0; nt < 8; ++nt) {
            const long r = rbase + mt * 16;
            const long c = cbase + nt * 8;
            float* Cp = Ob + r * 1536 + c;
            *(float2*)Cp = make_float2(acc[mt][nt][0], acc[mt][nt][1]);
            *(float2*)(Cp + 8L * 1536) = make_float2(acc[mt][nt][2], acc[mt][nt][3]);
        }
}

// ---------------------------------------------------------------------------
// split + transpose + passthrough
// ---------------------------------------------------------------------------
__global__ void split_tr(const float* __restrict__ X,
                         bf16* __restrict__ Xhi, bf16* __restrict__ Xlo,
                         __half* __restrict__ XTh,
                         float* __restrict__ outbase)
{
    const int b = blockIdx.z;
    const int d0 = blockIdx.x * 32, l0 = blockIdx.y * 32;
    const int tx = threadIdx.x, ty = threadIdx.y;
    __shared__ __half thi[32][33];

#pragma unroll
    for (int i = 0; i < 4; ++i) {
        const int ll = ty + 8 * i;
        const size_t idx = (size_t)b * LL * DD + (size_t)(l0 + ll) * DD + d0 + tx;
        const float x = X[idx];
        const bf16 h = __float2bfloat16(x);
        Xhi[idx] = h;
        Xlo[idx] = __float2bfloat16(x - __bfloat162float(h));
        thi[ll][tx] = __float2half(x);
        outbase[(size_t)(b * LL + l0 + ll) * 1536 + d0 + tx] = x;
    }
    __syncthreads();
#pragma unroll
    for (int i = 0; i < 4; ++i) {
        const int dd = ty + 8 * i;
        XTh[(size_t)b * DD * LL + (size_t)(d0 + dd) * LL + l0 + tx] = thi[tx][dd];
    }
}

__global__ void split_w(const float* __restrict__ Wl, const float* __restrict__ Wr,
                        bf16* __restrict__ Wlh, bf16* __restrict__ Wll,
                        bf16* __restrict__ Wrh, bf16* __restrict__ Wrl)
{
    const int i = blockIdx.x * blockDim.x + threadIdx.x;
    if (i < DD * DD) {
        float x = Wl[i];
        bf16 h = __float2bfloat16(x);
        Wlh[i] = h; Wll[i] = __float2bfloat16(x - __bfloat162float(h));
        x = Wr[i];
        h = __float2bfloat16(x);
        Wrh[i] = h; Wrl[i] = __float2bfloat16(x - __bfloat162float(h));
    }
}

// ---------------------------------------------------------------------------
// softmax stats
// ---------------------------------------------------------------------------
__global__ void row_stats(const float* __restrict__ S, float* __restrict__ rowc)
{
    const int row = blockIdx.x;
    const float* Sp = S + (size_t)row * LL;
    const int t = threadIdx.x;
    float v[4];
    float m = -1e30f;
#pragma unroll
    for (int i = 0; i < 4; ++i) { v[i] = Sp[t + i * 256]; m = fmaxf(m, v[i]); }
    __shared__ float red[256];
    red[t] = m; __syncthreads();
    for (int s = 128; s > 0; s >>= 1) {
        if (t < s) red[t] = fmaxf(red[t], red[t + s]);
        __syncthreads();
    }
    const float M = red[0];
    __syncthreads();
    float sum = 0.0f;
#pragma unroll
    for (int i = 0; i < 4; ++i) sum += __expf(v[i] - M);
    red[t] = sum; __syncthreads();
    for (int s = 128; s > 0; s >>= 1) {
        if (t < s) red[t] += red[t + s];
        __syncthreads();
    }
    if (t == 0) rowc[row] = M + __logf(red[0]);
}

__global__ void col_stats(const float* __restrict__ S, float* __restrict__ colc)
{
    const int b = blockIdx.y;
    const int tx = threadIdx.x, ty = threadIdx.y;
    const int c = blockIdx.x * 32 + tx;
    const float* Sp = S + (size_t)b * LL * LL + c;

    float m = -1e30f, s = 0.0f;
    for (int l = ty * 128; l < (ty + 1) * 128; ++l) {
        const float x = Sp[(size_t)l * LL] * INV_SCALE;
        if (x > m) { s = s * __expf(m - x) + 1.0f; m = x; }
        else s += __expf(x - m);
    }
    __shared__ float redm[8][32], reds[8][32];
    redm[ty][tx] = m; reds[ty][tx] = s;
    __syncthreads();
    if (ty == 0) {
        float M = redm[0][tx];
#pragma unroll
        for (int i = 1; i < 8; ++i) M = fmaxf(M, redm[i][tx]);
        float ss = 0.0f;
#pragma unroll
        for (int i = 0; i < 8; ++i) ss += reds[i][tx] * __expf(redm[i][tx] - M);
        colc[b * LL + c] = M + __logf(ss);
    }
}

// normalize into P1 fp16 [l][r] and P2T fp16 [r][l]
__global__ void transform(const float* __restrict__ S,
                          const float* __restrict__ rowc,
                          const float* __restrict__ colc,
                          __half* __restrict__ P1, __half* __restrict__ P2T)
{
    const int n = blockIdx.z;
    const size_t base = (size_t)n * LL * LL;
    const int l0 = blockIdx.y * 32, r0 = blockIdx.x * 32;
    const int tx = threadIdx.x, ty = threadIdx.y;
    __shared__ float tile[32][33];
    const float cc = colc[n * LL + r0 + tx];

#pragma unroll
    for (int i = 0; i < 4; ++i) {
        const int ll = ty + 8 * i;
        const size_t idx = base + (size_t)(l0 + ll) * LL + r0 + tx;
        const float s = S[idx];
        P1[idx] = __float2half(__expf(s - rowc[n * LL + l0 + ll]));
        tile[ll][tx] = s * INV_SCALE - cc;
    }
    __syncthreads();
#pragma unroll
    for (int i = 0; i < 4; ++i) {
        const int rr = ty + 8 * i;
        P2T[base + (size_t)(r0 + rr) * LL + l0 + tx] = __float2half(__expf(tile[tx][rr]));
    }
}

// ---------------------------------------------------------------------------
// launch
// ---------------------------------------------------------------------------
extern "C" void kernel_launch(void* const* d_in, const int* in_sizes, int n_in,
                              void* d_out, int out_size)
{
    const float* lhs = (const float*)d_in[0];
    const float* rhs = (const float*)d_in[1];
    const float* Wl  = (const float*)d_in[2];
    const float* Wr  = (const float*)d_in[3];
    float* out = (float*)d_out;

    bf16 *p_lhs_h, *p_lhs_l, *p_rhs_h, *p_rhs_l;
    __half *p_lhsT_h, *p_rhsT_h;
    bf16 *p_Wl_h, *p_Wl_l, *p_Wr_h, *p_Wr_l;
    bf16 *p_L_h, *p_L_l, *p_R_h, *p_R_l;
    __half *p_P1, *p_P2T;
    float *pS, *prc, *pcc;
    cudaGetSymbolAddress((void**)&p_lhs_h, s_lhs_hi);
    cudaGetSymbolAddress((void**)&p_lhs_l, s_lhs_lo);
    cudaGetSymbolAddress((void**)&p_rhs_h, s_rhs_hi);
    cudaGetSymbolAddress((void**)&p_rhs_l, s_rhs_lo);
    cudaGetSymbolAddress((void**)&p_lhsT_h, s_lhsT_h);
    cudaGetSymbolAddress((void**)&p_rhsT_h, s_rhsT_h);
    cudaGetSymbolAddress((void**)&p_Wl_h, s_Wl_hi);
    cudaGetSymbolAddress((void**)&p_Wl_l, s_Wl_lo);
    cudaGetSymbolAddress((void**)&p_Wr_h, s_Wr_hi);
    cudaGetSymbolAddress((void**)&p_Wr_l, s_Wr_lo);
    cudaGetSymbolAddress((void**)&p_L_h, g_L_hi);
    cudaGetSymbolAddress((void**)&p_L_l, g_L_lo);
    cudaGetSymbolAddress((void**)&p_R_h, g_R_hi);
    cudaGetSymbolAddress((void**)&p_R_l, g_R_lo);
    cudaGetSymbolAddress((void**)&p_P1, g_P1);
    cudaGetSymbolAddress((void**)&p_P2T, g_P2T);
    cudaGetSymbolAddress((void**)&pS, g_S);
    cudaGetSymbolAddress((void**)&prc, g_rowc);
    cudaGetSymbolAddress((void**)&pcc, g_colc);

    const int SMEM4 = 3 * STAGE4;  // 96 KB
    const int SMEMA = 3 * STAGEA;  // 96 KB
    cudaFuncSetAttribute(mm_bf16x3<0>, cudaFuncAttributeMaxDynamicSharedMemorySize, SMEM4);
    cudaFuncSetAttribute(mm_bf16x3<1>, cudaFuncAttributeMaxDynamicSharedMemorySize, SMEM4);
    cudaFuncSetAttribute(mm_f16_apply, cudaFuncAttributeMaxDynamicSharedMemorySize, SMEMA);

    // 1. operand prep: split + transpose + passthrough copy
    split_tr<<<dim3(DD / 32, LL / 32, BB), dim3(32, 8)>>>(
        lhs, p_lhs_h, p_lhs_l, p_lhsT_h, out);
    split_tr<<<dim3(DD / 32, LL / 32, BB), dim3(32, 8)>>>(
        rhs, p_rhs_h, p_rhs_l, p_rhsT_h, out + (size_t)BB * LL * 1536);
    split_w<<<(DD * DD + 255) / 256, 256>>>(Wl, Wr, p_Wl_h, p_Wl_l, p_Wr_h, p_Wr_l);

    // 2. both projections in ONE launch (z=0: lhs@Wl, z=1: rhs@Wr)
    mm_bf16x3<1><<<dim3(DD / 128, (BB * LL) / 128, 2), 256, SMEM4>>>(
        p_lhs_h, p_lhs_l, p_Wl_h, p_Wl_l,
        p_rhs_h, p_rhs_l, p_Wr_h, p_Wr_l,
        0, 0, DD, DD / 32, 1,
        nullptr, 0, DD, p_L_h, p_L_l, p_R_h, p_R_l);

    // 3. scores
    mm_bf16x3<0><<<dim3(LL / 128, LL / 128, BB), 256, SMEM4>>>(
        p_L_h, p_L_l, p_R_h, p_R_l,
        nullptr, nullptr, nullptr, nullptr,
        (long)LL * DD, (long)LL * DD, DD, DD / 32, 0,
        pS, (long)LL * LL, LL, nullptr, nullptr, nullptr, nullptr);

    // 4. softmax stats + normalized fp16 probabilities
    row_stats<<<BB * LL, 256>>>(pS, prc);
    col_stats<<<dim3(LL / 32, BB), dim3(32, 8)>>>(pS, pcc);
    transform<<<dim3(LL / 32, LL / 32, BB), dim3(32, 8)>>>(pS, prc, pcc, p_P1, p_P2T);

    // 5. both applies in ONE launch (z<8: dir 0, z>=8: dir 1), V fp16 single
    mm_f16_apply<<<dim3(DD / 128, LL / 128, 2 * BB), 256, SMEMA>>>(
        p_P1, p_rhsT_h, out,
        p_P2T, p_lhsT_h, out + (size_t)BB * LL * 1536);
}